// round 2
// baseline (speedup 1.0000x reference)
#include <cuda_runtime.h>
#include <math.h>

#define N_MAX 500000
#define B_MAX 10000
#define D 256

// ---------------- scratch (static device globals; no runtime alloc) --------
__device__ float g_gate[N_MAX];
__device__ float g_alpha[N_MAX];
__device__ int   g_batch32[N_MAX];
__device__ int   g_segstart[B_MAX + 1];
__device__ float g_xg[(size_t)B_MAX * D];
__device__ int   g_is64;

// ---------------- dtype detection for batch (int32 vs int64) ----------------
// Sample the buffer as int64 at indices < n/2 (safe under both layouts).
// Sorted batch over [0,B): if dtype is int32, the int64 view at mid indices
// has a nonzero high word -> value >= 2^32.
__global__ void k_detect(const void* __restrict__ batch, int n) {
    const unsigned long long* p = (const unsigned long long*)batch;
    unsigned long long v = 0;
    int half = n / 2;
    v |= p[half - 1];
    v |= p[half / 2];
    v |= p[half / 4];
    g_is64 = (v < 0x80000000ull) ? 1 : 0;
}

// ---------------- segment boundaries from sorted batch ----------------------
__global__ void k_seg(const void* __restrict__ batch, int n, int b) {
    int i = blockIdx.x * blockDim.x + threadIdx.x;
    if (i >= n) return;
    const int is64 = g_is64;
    int bi, prev;
    if (is64) {
        bi = (int)((const long long*)batch)[i];
        prev = (i == 0) ? -1 : (int)((const long long*)batch)[i - 1];
    } else {
        bi = ((const int*)batch)[i];
        prev = (i == 0) ? -1 : ((const int*)batch)[i - 1];
    }
    // defensive clamp: wrong value -> wrong answer (diagnosable), not a crash
    if (bi < 0) bi = 0;
    if (bi > b - 1) bi = b - 1;
    if (prev < -1) prev = -1;
    if (prev > b - 1) prev = b - 1;
    g_batch32[i] = bi;
    for (int bb = prev + 1; bb <= bi; ++bb) g_segstart[bb] = i;
    if (i == n - 1) {
        for (int bb = bi + 1; bb <= b; ++bb) g_segstart[bb] = n;
    }
}

// ---------------- gate = x @ W_gate + b_gate (warp per node) ----------------
__global__ void k_gate(const float* __restrict__ x, const float* __restrict__ Wg,
                       const float* __restrict__ bg, int n) {
    int warp = (blockIdx.x * blockDim.x + threadIdx.x) >> 5;
    int lane = threadIdx.x & 31;
    if (warp >= n) return;
    const float4* xr = (const float4*)(x + (size_t)warp * D);
    const float4* wr = (const float4*)Wg;
    float acc = 0.f;
#pragma unroll
    for (int i = 0; i < 2; i++) {
        float4 a = xr[lane + 32 * i];
        float4 w = wr[lane + 32 * i];
        acc += a.x * w.x + a.y * w.y + a.z * w.z + a.w * w.w;
    }
#pragma unroll
    for (int o = 16; o; o >>= 1) acc += __shfl_xor_sync(0xffffffffu, acc, o);
    if (lane == 0) g_gate[warp] = acc + bg[0];
}

// ---------------- per-graph softmax weights (warp per graph) ----------------
__global__ void k_alpha(int b) {
    int w = (blockIdx.x * blockDim.x + threadIdx.x) >> 5;
    int lane = threadIdx.x & 31;
    if (w >= b) return;
    int s = g_segstart[w], e = g_segstart[w + 1];
    if (s >= e) return;
    float m = -1e30f;
    for (int i = s + lane; i < e; i += 32) m = fmaxf(m, g_gate[i]);
#pragma unroll
    for (int o = 16; o; o >>= 1) m = fmaxf(m, __shfl_xor_sync(0xffffffffu, m, o));
    float sum = 0.f;
    for (int i = s + lane; i < e; i += 32) sum += expf(g_gate[i] - m);
#pragma unroll
    for (int o = 16; o; o >>= 1) sum += __shfl_xor_sync(0xffffffffu, sum, o);
    float inv = 1.0f / sum;
    for (int i = s + lane; i < e; i += 32) g_alpha[i] = expf(g_gate[i] - m) * inv;
}

// ---------------- zero xg accumulator ---------------------------------------
__global__ void k_zero(int total4) {
    int i = blockIdx.x * blockDim.x + threadIdx.x;
    if (i < total4) ((float4*)g_xg)[i] = make_float4(0.f, 0.f, 0.f, 0.f);
}

// ---------------- main fused GEMM: xg += alpha * lrelu(x @ W_feat + b) ------
#define BM 128
#define BN 128
#define BK 16
#define BMP 132
#define TM 8
#define TN 8

__global__ void __launch_bounds__(256) k_main(const float* __restrict__ x,
                                              const float* __restrict__ Wf,
                                              const float* __restrict__ bf, int n) {
    __shared__ float As[2][BK * BMP];
    __shared__ float Bs[2][BK * BN];
    __shared__ int   sBatch[BM];
    __shared__ float sAlpha[BM];

    const int tid = threadIdx.x;
    const int tx = tid & 15;         // 0..15 -> col group
    const int ty = tid >> 4;         // 0..15 -> row group
    const int m0 = blockIdx.x * BM;
    const int n0 = blockIdx.y * BN;

    if (tid < BM) {
        int r = m0 + tid;
        sBatch[tid] = (r < n) ? g_batch32[r] : -1;
    } else {
        int r = m0 + tid - BM;
        sAlpha[tid - BM] = (r < n) ? g_alpha[r] : 0.f;
    }

    const int a_r = tid >> 2;
    const int a_k = (tid & 3) * 4;
    const int b_k = tid >> 5;
    const int b_c = (tid & 31) * 4;

    float acc[TM][TN];
#pragma unroll
    for (int i = 0; i < TM; i++)
#pragma unroll
        for (int j = 0; j < TN; j++) acc[i][j] = 0.f;

    float4 va[2], vb[2];
    const int NST = D / BK;  // 16

#pragma unroll
    for (int i = 0; i < 2; i++) {
        int gr = m0 + a_r + 64 * i;
        va[i] = (gr < n) ? *(const float4*)(x + (size_t)gr * D + a_k)
                         : make_float4(0.f, 0.f, 0.f, 0.f);
        vb[i] = *(const float4*)(Wf + (size_t)(b_k + 8 * i) * D + n0 + b_c);
    }
    int buf = 0;
#pragma unroll
    for (int i = 0; i < 2; i++) {
        int r = a_r + 64 * i;
        As[buf][(a_k + 0) * BMP + r] = va[i].x;
        As[buf][(a_k + 1) * BMP + r] = va[i].y;
        As[buf][(a_k + 2) * BMP + r] = va[i].z;
        As[buf][(a_k + 3) * BMP + r] = va[i].w;
        *(float4*)&Bs[buf][(b_k + 8 * i) * BN + b_c] = vb[i];
    }
    __syncthreads();

    for (int t = 0; t < NST; ++t) {
        if (t + 1 < NST) {
            int kk = (t + 1) * BK;
#pragma unroll
            for (int i = 0; i < 2; i++) {
                int gr = m0 + a_r + 64 * i;
                va[i] = (gr < n) ? *(const float4*)(x + (size_t)gr * D + kk + a_k)
                                 : make_float4(0.f, 0.f, 0.f, 0.f);
                vb[i] = *(const float4*)(Wf + (size_t)(kk + b_k + 8 * i) * D + n0 + b_c);
            }
        }
        float ra[TM], rb[TN];
#pragma unroll
        for (int k = 0; k < BK; k++) {
            *(float4*)&ra[0] = *(float4*)&As[buf][k * BMP + ty * 8];
            *(float4*)&ra[4] = *(float4*)&As[buf][k * BMP + ty * 8 + 4];
            *(float4*)&rb[0] = *(float4*)&Bs[buf][k * BN + tx * 8];
            *(float4*)&rb[4] = *(float4*)&Bs[buf][k * BN + tx * 8 + 4];
#pragma unroll
            for (int i = 0; i < TM; i++)
#pragma unroll
                for (int j = 0; j < TN; j++) acc[i][j] += ra[i] * rb[j];
        }
        if (t + 1 < NST) {
            int nb = buf ^ 1;
#pragma unroll
            for (int i = 0; i < 2; i++) {
                int r = a_r + 64 * i;
                As[nb][(a_k + 0) * BMP + r] = va[i].x;
                As[nb][(a_k + 1) * BMP + r] = va[i].y;
                As[nb][(a_k + 2) * BMP + r] = va[i].z;
                As[nb][(a_k + 3) * BMP + r] = va[i].w;
                *(float4*)&Bs[nb][(b_k + 8 * i) * BN + b_c] = vb[i];
            }
        }
        __syncthreads();
        buf ^= 1;
    }

    // epilogue: bias + leaky_relu + alpha weighting + segment-run atomics
    const int col0 = n0 + tx * 8;
    float bias[TN];
    *(float4*)&bias[0] = *(const float4*)(bf + col0);
    *(float4*)&bias[4] = *(const float4*)(bf + col0 + 4);

    float sum[TN];
#pragma unroll
    for (int j = 0; j < TN; j++) sum[j] = 0.f;
    int prevb = -2;
#pragma unroll
    for (int i = 0; i < TM; i++) {
        int r = ty * 8 + i;
        int b = sBatch[r];
        if (b != prevb) {
            if (prevb >= 0) {
#pragma unroll
                for (int j = 0; j < TN; j++)
                    atomicAdd(&g_xg[(size_t)prevb * D + col0 + j], sum[j]);
            }
#pragma unroll
            for (int j = 0; j < TN; j++) sum[j] = 0.f;
            prevb = b;
        }
        if (b >= 0) {
            float al = sAlpha[r];
#pragma unroll
            for (int j = 0; j < TN; j++) {
                float v = acc[i][j] + bias[j];
                v = (v >= 0.f) ? v : 0.01f * v;
                sum[j] += v * al;
            }
        }
    }
    if (prevb >= 0) {
#pragma unroll
        for (int j = 0; j < TN; j++)
            atomicAdd(&g_xg[(size_t)prevb * D + col0 + j], sum[j]);
    }
}

// ---------------- final: out = lrelu([xg | xg_old] @ W_t + b_t) + xg_old ----
__global__ void __launch_bounds__(256) k_final(const float* __restrict__ xg_old,
                                               const float* __restrict__ Wt,
                                               const float* __restrict__ bt,
                                               float* __restrict__ out, int bsz) {
    __shared__ float As[2][BK * BMP];
    __shared__ float Bs[2][BK * BN];

    const int tid = threadIdx.x;
    const int tx = tid & 15;
    const int ty = tid >> 4;
    const int m0 = blockIdx.x * BM;
    const int n0 = blockIdx.y * BN;

    const int a_r = tid >> 2;
    const int a_k = (tid & 3) * 4;
    const int b_k = tid >> 5;
    const int b_c = (tid & 31) * 4;

    float acc[TM][TN];
#pragma unroll
    for (int i = 0; i < TM; i++)
#pragma unroll
        for (int j = 0; j < TN; j++) acc[i][j] = 0.f;

    const int K2 = 2 * D;       // 512
    const int NST = K2 / BK;    // 32
    float4 va[2], vb[2];

    auto loadA = [&](int gr, int c) -> float4 {
        if (gr >= bsz) return make_float4(0.f, 0.f, 0.f, 0.f);
        if (c < D) return *(const float4*)(g_xg + (size_t)gr * D + c);
        return *(const float4*)(xg_old + (size_t)gr * D + (c - D));
    };

#pragma unroll
    for (int i = 0; i < 2; i++) {
        va[i] = loadA(m0 + a_r + 64 * i, a_k);
        vb[i] = *(const float4*)(Wt + (size_t)(b_k + 8 * i) * D + n0 + b_c);
    }
    int buf = 0;
#pragma unroll
    for (int i = 0; i < 2; i++) {
        int r = a_r + 64 * i;
        As[buf][(a_k + 0) * BMP + r] = va[i].x;
        As[buf][(a_k + 1) * BMP + r] = va[i].y;
        As[buf][(a_k + 2) * BMP + r] = va[i].z;
        As[buf][(a_k + 3) * BMP + r] = va[i].w;
        *(float4*)&Bs[buf][(b_k + 8 * i) * BN + b_c] = vb[i];
    }
    __syncthreads();

    for (int t = 0; t < NST; ++t) {
        if (t + 1 < NST) {
            int kk = (t + 1) * BK;
#pragma unroll
            for (int i = 0; i < 2; i++) {
                va[i] = loadA(m0 + a_r + 64 * i, kk + a_k);
                vb[i] = *(const float4*)(Wt + (size_t)(kk + b_k + 8 * i) * D + n0 + b_c);
            }
        }
        float ra[TM], rb[TN];
#pragma unroll
        for (int k = 0; k < BK; k++) {
            *(float4*)&ra[0] = *(float4*)&As[buf][k * BMP + ty * 8];
            *(float4*)&ra[4] = *(float4*)&As[buf][k * BMP + ty * 8 + 4];
            *(float4*)&rb[0] = *(float4*)&Bs[buf][k * BN + tx * 8];
            *(float4*)&rb[4] = *(float4*)&Bs[buf][k * BN + tx * 8 + 4];
#pragma unroll
            for (int i = 0; i < TM; i++)
#pragma unroll
                for (int j = 0; j < TN; j++) acc[i][j] += ra[i] * rb[j];
        }
        if (t + 1 < NST) {
            int nb = buf ^ 1;
#pragma unroll
            for (int i = 0; i < 2; i++) {
                int r = a_r + 64 * i;
                As[nb][(a_k + 0) * BMP + r] = va[i].x;
                As[nb][(a_k + 1) * BMP + r] = va[i].y;
                As[nb][(a_k + 2) * BMP + r] = va[i].z;
                As[nb][(a_k + 3) * BMP + r] = va[i].w;
                *(float4*)&Bs[nb][(b_k + 8 * i) * BN + b_c] = vb[i];
            }
        }
        __syncthreads();
        buf ^= 1;
    }

    const int col0 = n0 + tx * 8;
    float bias[TN];
    *(float4*)&bias[0] = *(const float4*)(bt + col0);
    *(float4*)&bias[4] = *(const float4*)(bt + col0 + 4);

#pragma unroll
    for (int i = 0; i < TM; i++) {
        int gr = m0 + ty * 8 + i;
        if (gr >= bsz) continue;
        float res[TN];
        *(float4*)&res[0] = *(const float4*)(xg_old + (size_t)gr * D + col0);
        *(float4*)&res[4] = *(const float4*)(xg_old + (size_t)gr * D + col0 + 4);
        float o[TN];
#pragma unroll
        for (int j = 0; j < TN; j++) {
            float v = acc[i][j] + bias[j];
            v = (v >= 0.f) ? v : 0.01f * v;
            o[j] = v + res[j];
        }
        *(float4*)(out + (size_t)gr * D + col0) = *(float4*)&o[0];
        *(float4*)(out + (size_t)gr * D + col0 + 4) = *(float4*)&o[4];
    }
}

// ---------------- launcher ---------------------------------------------------
extern "C" void kernel_launch(void* const* d_in, const int* in_sizes, int n_in,
                              void* d_out, int out_size) {
    const float* xg_old = (const float*)d_in[0];
    const float* x      = (const float*)d_in[1];
    const void*  batch  = d_in[2];
    const float* W_gate = (const float*)d_in[3];
    const float* b_gate = (const float*)d_in[4];
    const float* W_feat = (const float*)d_in[5];
    const float* b_feat = (const float*)d_in[6];
    const float* W_t    = (const float*)d_in[7];
    const float* b_t    = (const float*)d_in[8];
    float*       out    = (float*)d_out;

    int n = in_sizes[2];          // N nodes
    int b = in_sizes[0] / D;      // B graphs
    if (n > N_MAX) n = N_MAX;
    if (b > B_MAX) b = B_MAX;

    k_detect<<<1, 1>>>(batch, n);
    k_seg<<<(n + 255) / 256, 256>>>(batch, n, b);
    k_gate<<<(n + 7) / 8, 256>>>(x, W_gate, b_gate, n);
    k_alpha<<<(b + 7) / 8, 256>>>(b);
    k_zero<<<(b * (D / 4) + 255) / 256, 256>>>(b * (D / 4));

    dim3 gm((n + BM - 1) / BM, D / BN);
    k_main<<<gm, 256>>>(x, W_feat, b_feat, n);

    dim3 gf((b + BM - 1) / BM, D / BN);
    k_final<<<gf, 256>>>(xg_old, W_t, b_t, out, b);
}

// round 7
// speedup vs baseline: 1.1880x; 1.1880x over previous
#include <cuda_runtime.h>
#include <cuda_fp16.h>
#include <math.h>
#include <stdint.h>

#define N_MAX 500000
#define B_MAX 10000
#define D 256

// ---------------- scratch (static device globals; no runtime alloc) --------
__device__ float g_gate[N_MAX];
__device__ float g_alpha[N_MAX];
__device__ int   g_batch32[N_MAX];
__device__ int   g_segstart[B_MAX + 1];
__device__ float g_xg[(size_t)B_MAX * D];
__device__ int   g_is64;

// ---------------- helpers ----------------------------------------------------
__device__ __forceinline__ uint32_t smem_u32(const void* p) {
    uint32_t a;
    asm("{ .reg .u64 t; cvta.to.shared.u64 t, %1; cvt.u32.u64 %0, t; }"
        : "=r"(a) : "l"(p));
    return a;
}

#define LDSM_X4(r0, r1, r2, r3, addr) \
    asm volatile("ldmatrix.sync.aligned.m8n8.x4.shared.b16 {%0,%1,%2,%3}, [%4];" \
                 : "=r"(r0), "=r"(r1), "=r"(r2), "=r"(r3) : "r"(addr))

#define MMA16816(c0, c1, c2, c3, a0, a1, a2, a3, b0, b1) \
    asm volatile("mma.sync.aligned.m16n8k16.row.col.f32.f16.f16.f32 " \
                 "{%0,%1,%2,%3}, {%4,%5,%6,%7}, {%8,%9}, {%0,%1,%2,%3};" \
                 : "+f"(c0), "+f"(c1), "+f"(c2), "+f"(c3) \
                 : "r"(a0), "r"(a1), "r"(a2), "r"(a3), "r"(b0), "r"(b1))

__device__ __forceinline__ uint32_t pack_hi2(float x, float y) {
    __half2 h = __halves2half2(__float2half_rn(x), __float2half_rn(y));
    return *(uint32_t*)&h;
}
__device__ __forceinline__ uint32_t pack_lo2(float x, float y, uint32_t hi) {
    __half2 h = *(__half2*)&hi;
    float2 f = __half22float2(h);
    __half2 l = __halves2half2(__float2half_rn(x - f.x), __float2half_rn(y - f.y));
    return *(uint32_t*)&l;
}

// ---------------- dtype detection for batch (int32 vs int64) ----------------
__global__ void k_detect(const void* __restrict__ batch, int n) {
    const unsigned long long* p = (const unsigned long long*)batch;
    unsigned long long v = 0;
    int half = n / 2;
    v |= p[half - 1];
    v |= p[half / 2];
    v |= p[half / 4];
    g_is64 = (v < 0x80000000ull) ? 1 : 0;
}

// ---------------- segment boundaries from sorted batch ----------------------
__global__ void k_seg(const void* __restrict__ batch, int n, int b) {
    int i = blockIdx.x * blockDim.x + threadIdx.x;
    if (i >= n) return;
    const int is64 = g_is64;
    int bi, prev;
    if (is64) {
        bi = (int)((const long long*)batch)[i];
        prev = (i == 0) ? -1 : (int)((const long long*)batch)[i - 1];
    } else {
        bi = ((const int*)batch)[i];
        prev = (i == 0) ? -1 : ((const int*)batch)[i - 1];
    }
    if (bi < 0) bi = 0;
    if (bi > b - 1) bi = b - 1;
    if (prev < -1) prev = -1;
    if (prev > b - 1) prev = b - 1;
    g_batch32[i] = bi;
    for (int bb = prev + 1; bb <= bi; ++bb) g_segstart[bb] = i;
    if (i == n - 1) {
        for (int bb = bi + 1; bb <= b; ++bb) g_segstart[bb] = n;
    }
}

// ---------------- gate = x @ W_gate + b_gate (warp per node) ----------------
__global__ void k_gate(const float* __restrict__ x, const float* __restrict__ Wg,
                       const float* __restrict__ bg, int n) {
    int warp = (blockIdx.x * blockDim.x + threadIdx.x) >> 5;
    int lane = threadIdx.x & 31;
    if (warp >= n) return;
    const float4* xr = (const float4*)(x + (size_t)warp * D);
    const float4* wr = (const float4*)Wg;
    float acc = 0.f;
#pragma unroll
    for (int i = 0; i < 2; i++) {
        float4 a = xr[lane + 32 * i];
        float4 w = wr[lane + 32 * i];
        acc += a.x * w.x + a.y * w.y + a.z * w.z + a.w * w.w;
    }
#pragma unroll
    for (int o = 16; o; o >>= 1) acc += __shfl_xor_sync(0xffffffffu, acc, o);
    if (lane == 0) g_gate[warp] = acc + bg[0];
}

// ---------------- per-graph softmax weights (warp per graph) ----------------
__global__ void k_alpha(int b) {
    int w = (blockIdx.x * blockDim.x + threadIdx.x) >> 5;
    int lane = threadIdx.x & 31;
    if (w >= b) return;
    int s = g_segstart[w], e = g_segstart[w + 1];
    if (s >= e) return;
    float m = -1e30f;
    for (int i = s + lane; i < e; i += 32) m = fmaxf(m, g_gate[i]);
#pragma unroll
    for (int o = 16; o; o >>= 1) m = fmaxf(m, __shfl_xor_sync(0xffffffffu, m, o));
    float sum = 0.f;
    for (int i = s + lane; i < e; i += 32) sum += expf(g_gate[i] - m);
#pragma unroll
    for (int o = 16; o; o >>= 1) sum += __shfl_xor_sync(0xffffffffu, sum, o);
    float inv = 1.0f / sum;
    for (int i = s + lane; i < e; i += 32) g_alpha[i] = expf(g_gate[i] - m) * inv;
}

// ---------------- zero xg accumulator ---------------------------------------
__global__ void k_zero(int total4) {
    int i = blockIdx.x * blockDim.x + threadIdx.x;
    if (i < total4) ((float4*)g_xg)[i] = make_float4(0.f, 0.f, 0.f, 0.f);
}

// ============ mma.sync main GEMM: xg += alpha * lrelu(x @ W_feat + b) =======
// CTA 128x128, K=256 in 4 chunks of 64. fp16 hi/lo 3-term split, fp32 accum.
// smem layout (bytes): Ahi[128][72]h, Alo, Bhi[128][72]h, Blo  (stride 144B)
#define LDKB 144
#define OFF_AHI 0
#define OFF_ALO 18432
#define OFF_BHI 36864
#define OFF_BLO 55296
#define OFF_BATCH 73728
#define OFF_ALPHA 74240
#define OFF_BIAS  74752
#define SMEM_MAIN 75264
#define SD_STRIDE 130

__global__ void __launch_bounds__(256, 1)
k_main_mma(const float* __restrict__ x, const float* __restrict__ Wf,
           const float* __restrict__ bf, int n) {
    extern __shared__ char smem[];
    const int tid = threadIdx.x;
    const int m0 = blockIdx.y * 128;
    const int n0 = blockIdx.x * 128;
    const uint32_t sbase = smem_u32(smem);
    int*   sBatch = (int*)(smem + OFF_BATCH);
    float* sAlpha = (float*)(smem + OFF_ALPHA);
    float* sBias  = (float*)(smem + OFF_BIAS);
    float* sD     = (float*)smem;   // reused after compute (128 x 130 fp32)

    if (tid < 128) {
        int r = m0 + tid;
        sBatch[tid] = (r < n) ? g_batch32[r] : -1;
        sBias[tid]  = bf[n0 + tid];
    } else {
        int r = m0 + tid - 128;
        sAlpha[tid - 128] = (r < n) ? g_alpha[r] : 0.f;
    }

    // loader mappings
    const int ar  = tid >> 1;            // A row 0..127
    const int akq = (tid & 1) * 32;      // A k sub-offset
    const int bk  = (tid & 31) * 2;      // B k row (even), lane-distinct
    const int bn0 = (tid >> 5) * 16;     // B n group (warp-uniform)

    const bool avalid = (m0 + ar) < n;
    const float* xrow = x + (size_t)(m0 + ar) * D + akq;

    // warp tiling: 2 (M) x 4 (N) warps, warp tile 64x32
    const int wid = tid >> 5, lane = tid & 31;
    const int wm = wid >> 2, wn = wid & 3;

    float c[4][4][4];
#pragma unroll
    for (int mi = 0; mi < 4; mi++)
#pragma unroll
        for (int nt = 0; nt < 4; nt++)
#pragma unroll
            for (int q = 0; q < 4; q++) c[mi][nt][q] = 0.f;

    float4 va[8];

    // ---- prologue: load + convert + STS chunk 0 ----
    {
#pragma unroll
        for (int i = 0; i < 8; i++)
            va[i] = avalid ? *(const float4*)(xrow + 4 * i)
                           : make_float4(0.f, 0.f, 0.f, 0.f);
        float4 vb0[4], vb1[4];
        const float* w0 = Wf + (size_t)bk * D + n0 + bn0;
#pragma unroll
        for (int i = 0; i < 4; i++) {
            vb0[i] = *(const float4*)(w0 + 4 * i);
            vb1[i] = *(const float4*)(w0 + D + 4 * i);
        }
#pragma unroll
        for (int i = 0; i < 8; i++) {
            int kl = akq + 4 * i;
            float4 v = va[i];
            uint32_t h0 = pack_hi2(v.x, v.y), h1 = pack_hi2(v.z, v.w);
            uint32_t l0 = pack_lo2(v.x, v.y, h0), l1 = pack_lo2(v.z, v.w, h1);
            uint32_t off = (uint32_t)(ar * LDKB + kl * 2);
            asm volatile("st.shared.v2.b32 [%0], {%1,%2};"
                         :: "r"(sbase + OFF_AHI + off), "r"(h0), "r"(h1));
            asm volatile("st.shared.v2.b32 [%0], {%1,%2};"
                         :: "r"(sbase + OFF_ALO + off), "r"(l0), "r"(l1));
        }
#pragma unroll
        for (int i = 0; i < 4; i++) {
#pragma unroll
            for (int j = 0; j < 4; j++) {
                float e0 = (&vb0[i].x)[j], e1 = (&vb1[i].x)[j];
                uint32_t h = pack_hi2(e0, e1);
                uint32_t l = pack_lo2(e0, e1, h);
                uint32_t off = (uint32_t)((bn0 + 4 * i + j) * LDKB + bk * 2);
                asm volatile("st.shared.b32 [%0], %1;"
                             :: "r"(sbase + OFF_BHI + off), "r"(h));
                asm volatile("st.shared.b32 [%0], %1;"
                             :: "r"(sbase + OFF_BLO + off), "r"(l));
            }
        }
    }
    __syncthreads();

    // ldmatrix addresses (per-lane)
    const uint32_t a_off =
        (uint32_t)((wm * 64 + (lane & 15)) * LDKB + ((lane >> 4) << 3) * 2);
    const uint32_t b_off =
        (uint32_t)((wn * 32 + (lane & 15)) * LDKB + ((lane >> 4) << 3) * 2);

    for (int ch = 0; ch < 4; ch++) {
        // prefetch next A chunk into registers (consumed after compute)
        if (ch < 3) {
            const float* xp = xrow + (ch + 1) * 64;
#pragma unroll
            for (int i = 0; i < 8; i++)
                va[i] = avalid ? *(const float4*)(xp + 4 * i)
                               : make_float4(0.f, 0.f, 0.f, 0.f);
        }

        // ---- compute 4 k-steps from smem ----
#pragma unroll
        for (int ks = 0; ks < 4; ks++) {
            const uint32_t koff = (uint32_t)(ks * 32);  // 16 halves = 32B
            uint32_t ah[4][4], al[4][4], bh[2][4], bl[2][4];
#pragma unroll
            for (int mi = 0; mi < 4; mi++) {
                uint32_t adr = sbase + a_off + (uint32_t)(mi * 16 * LDKB) + koff;
                LDSM_X4(ah[mi][0], ah[mi][1], ah[mi][2], ah[mi][3], adr + OFF_AHI);
                LDSM_X4(al[mi][0], al[mi][1], al[mi][2], al[mi][3], adr + OFF_ALO);
            }
#pragma unroll
            for (int np = 0; np < 2; np++) {
                uint32_t adr = sbase + b_off + (uint32_t)(np * 16 * LDKB) + koff;
                LDSM_X4(bh[np][0], bh[np][1], bh[np][2], bh[np][3], adr + OFF_BHI);
                LDSM_X4(bl[np][0], bl[np][1], bl[np][2], bl[np][3], adr + OFF_BLO);
            }
#pragma unroll
            for (int mi = 0; mi < 4; mi++) {
#pragma unroll
                for (int np = 0; np < 2; np++) {
#pragma unroll
                    for (int t = 0; t < 2; t++) {
                        const int nt = np * 2 + t;
                        float* cc = c[mi][nt];
                        MMA16816(cc[0], cc[1], cc[2], cc[3],
                                 ah[mi][0], ah[mi][1], ah[mi][2], ah[mi][3],
                                 bh[np][t], bh[np][t + 2]);
                        MMA16816(cc[0], cc[1], cc[2], cc[3],
                                 al[mi][0], al[mi][1], al[mi][2], al[mi][3],
                                 bh[np][t], bh[np][t + 2]);
                        MMA16816(cc[0], cc[1], cc[2], cc[3],
                                 ah[mi][0], ah[mi][1], ah[mi][2], ah[mi][3],
                                 bl[np][t], bl[np][t + 2]);
                    }
                }
            }
        }
        __syncthreads();   // all warps done reading the stage

        if (ch < 3) {
            const int k0 = (ch + 1) * 64;
            float4 vb0[4], vb1[4];
            const float* w0 = Wf + (size_t)(k0 + bk) * D + n0 + bn0;
#pragma unroll
            for (int i = 0; i < 4; i++) {
                vb0[i] = *(const float4*)(w0 + 4 * i);
                vb1[i] = *(const float4*)(w0 + D + 4 * i);
            }
#pragma unroll
            for (int i = 0; i < 8; i++) {
                int kl = akq + 4 * i;
                float4 v = va[i];
                uint32_t h0 = pack_hi2(v.x, v.y), h1 = pack_hi2(v.z, v.w);
                uint32_t l0 = pack_lo2(v.x, v.y, h0), l1 = pack_lo2(v.z, v.w, h1);
                uint32_t off = (uint32_t)(ar * LDKB + kl * 2);
                asm volatile("st.shared.v2.b32 [%0], {%1,%2};"
                             :: "r"(sbase + OFF_AHI + off), "r"(h0), "r"(h1));
                asm volatile("st.shared.v2.b32 [%0], {%1,%2};"
                             :: "r"(sbase + OFF_ALO + off), "r"(l0), "r"(l1));
            }
#pragma unroll
            for (int i = 0; i < 4; i++) {
#pragma unroll
                for (int j = 0; j < 4; j++) {
                    float e0 = (&vb0[i].x)[j], e1 = (&vb1[i].x)[j];
                    uint32_t h = pack_hi2(e0, e1);
                    uint32_t l = pack_lo2(e0, e1, h);
                    uint32_t off = (uint32_t)((bn0 + 4 * i + j) * LDKB + bk * 2);
                    asm volatile("st.shared.b32 [%0], %1;"
                                 :: "r"(sbase + OFF_BHI + off), "r"(h));
                    asm volatile("st.shared.b32 [%0], %1;"
                                 :: "r"(sbase + OFF_BLO + off), "r"(l));
                }
            }
            __syncthreads();
        }
    }

    // ---- epilogue: bias + lrelu + alpha -> sD, then segment atomics ----
#pragma unroll
    for (int mi = 0; mi < 4; mi++) {
        const int r0 = wm * 64 + mi * 16 + (lane >> 2);
        const int r1 = r0 + 8;
        const float al0 = sAlpha[r0], al1 = sAlpha[r1];
#pragma unroll
        for (int nt = 0; nt < 4; nt++) {
            const int col = wn * 32 + nt * 8 + (lane & 3) * 2;
            const float b0 = sBias[col], b1 = sBias[col + 1];
            float v0 = c[mi][nt][0] + b0, v1 = c[mi][nt][1] + b1;
            float v2 = c[mi][nt][2] + b0, v3 = c[mi][nt][3] + b1;
            v0 = (v0 >= 0.f) ? v0 : 0.01f * v0;
            v1 = (v1 >= 0.f) ? v1 : 0.01f * v1;
            v2 = (v2 >= 0.f) ? v2 : 0.01f * v2;
            v3 = (v3 >= 0.f) ? v3 : 0.01f * v3;
            *(float2*)&sD[r0 * SD_STRIDE + col] = make_float2(v0 * al0, v1 * al0);
            *(float2*)&sD[r1 * SD_STRIDE + col] = make_float2(v2 * al1, v3 * al1);
        }
    }
    __syncthreads();

    {
        const int col = tid & 127, half = tid >> 7;
        const int rbeg = half * 64;
        float sum = 0.f;
        int prevb = -2;
        for (int r = 0; r < 64; r++) {
            int rr = rbeg + r;
            int b = sBatch[rr];
            if (b != prevb) {
                if (prevb >= 0)
                    atomicAdd(&g_xg[(size_t)prevb * D + n0 + col], sum);
                sum = 0.f;
                prevb = b;
            }
            if (b >= 0) sum += sD[rr * SD_STRIDE + col];
        }
        if (prevb >= 0) atomicAdd(&g_xg[(size_t)prevb * D + n0 + col], sum);
    }
}

// ---------------- final: out = lrelu([xg | xg_old] @ W_t + b_t) + xg_old ----
#define BM 128
#define BN 128
#define BK 16
#define BMP 132
#define TM 8
#define TN 8

__global__ void __launch_bounds__(256) k_final(const float* __restrict__ xg_old,
                                               const float* __restrict__ Wt,
                                               const float* __restrict__ bt,
                                               float* __restrict__ out, int bsz) {
    __shared__ float As[2][BK * BMP];
    __shared__ float Bs[2][BK * BN];

    const int tid = threadIdx.x;
    const int tx = tid & 15;
    const int ty = tid >> 4;
    const int m0 = blockIdx.x * BM;
    const int n0 = blockIdx.y * BN;

    const int a_r = tid >> 2;
    const int a_k = (tid & 3) * 4;
    const int b_k = tid >> 5;
    const int b_c = (tid & 31) * 4;

    float acc[TM][TN];
#pragma unroll
    for (int i = 0; i < TM; i++)
#pragma unroll
        for (int j = 0; j < TN; j++) acc[i][j] = 0.f;

    const int K2 = 2 * D;
    const int NST = K2 / BK;
    float4 va[2], vb[2];

    auto loadA = [&](int gr, int c) -> float4 {
        if (gr >= bsz) return make_float4(0.f, 0.f, 0.f, 0.f);
        if (c < D) return *(const float4*)(g_xg + (size_t)gr * D + c);
        return *(const float4*)(xg_old + (size_t)gr * D + (c - D));
    };

#pragma unroll
    for (int i = 0; i < 2; i++) {
        va[i] = loadA(m0 + a_r + 64 * i, a_k);
        vb[i] = *(const float4*)(Wt + (size_t)(b_k + 8 * i) * D + n0 + b_c);
    }
    int buf = 0;
#pragma unroll
    for (int i = 0; i < 2; i++) {
        int r = a_r + 64 * i;
        As[buf][(a_k + 0) * BMP + r] = va[i].x;
        As[buf][(a_k + 1) * BMP + r] = va[i].y;
        As[buf][(a_k + 2) * BMP + r] = va[i].z;
        As[buf][(a_k + 3) * BMP + r] = va[i].w;
        *(float4*)&Bs[buf][(b_k + 8 * i) * BN + b_c] = vb[i];
    }
    __syncthreads();

    for (int t = 0; t < NST; ++t) {
        if (t + 1 < NST) {
            int kk = (t + 1) * BK;
#pragma unroll
            for (int i = 0; i < 2; i++) {
                va[i] = loadA(m0 + a_r + 64 * i, kk + a_k);
                vb[i] = *(const float4*)(Wt + (size_t)(kk + b_k + 8 * i) * D + n0 + b_c);
            }
        }
        float ra[TM], rb[TN];
#pragma unroll
        for (int k = 0; k < BK; k++) {
            *(float4*)&ra[0] = *(float4*)&As[buf][k * BMP + ty * 8];
            *(float4*)&ra[4] = *(float4*)&As[buf][k * BMP + ty * 8 + 4];
            *(float4*)&rb[0] = *(float4*)&Bs[buf][k * BN + tx * 8];
            *(float4*)&rb[4] = *(float4*)&Bs[buf][k * BN + tx * 8 + 4];
#pragma unroll
            for (int i = 0; i < TM; i++)
#pragma unroll
                for (int j = 0; j < TN; j++) acc[i][j] += ra[i] * rb[j];
        }
        if (t + 1 < NST) {
            int nb = buf ^ 1;
#pragma unroll
            for (int i = 0; i < 2; i++) {
                int r = a_r + 64 * i;
                As[nb][(a_k + 0) * BMP + r] = va[i].x;
                As[nb][(a_k + 1) * BMP + r] = va[i].y;
                As[nb][(a_k + 2) * BMP + r] = va[i].z;
                As[nb][(a_k + 3) * BMP + r] = va[i].w;
                *(float4*)&Bs[nb][(b_k + 8 * i) * BN + b_c] = vb[i];
            }
        }
        __syncthreads();
        buf ^= 1;
    }

    const int col0 = n0 + tx * 8;
    float bias[TN];
    *(float4*)&bias[0] = *(const float4*)(bt + col0);
    *(float4*)&bias[4] = *(const float4*)(bt + col0 + 4);

#pragma unroll
    for (int i = 0; i < TM; i++) {
        int gr = m0 + ty * 8 + i;
        if (gr >= bsz) continue;
        float res[TN];
        *(float4*)&res[0] = *(const float4*)(xg_old + (size_t)gr * D + col0);
        *(float4*)&res[4] = *(const float4*)(xg_old + (size_t)gr * D + col0 + 4);
        float o[TN];
#pragma unroll
        for (int j = 0; j < TN; j++) {
            float v = acc[i][j] + bias[j];
            v = (v >= 0.f) ? v : 0.01f * v;
            o[j] = v + res[j];
        }
        *(float4*)(out + (size_t)gr * D + col0) = *(float4*)&o[0];
        *(float4*)(out + (size_t)gr * D + col0 + 4) = *(float4*)&o[4];
    }
}

// ---------------- launcher ---------------------------------------------------
extern "C" void kernel_launch(void* const* d_in, const int* in_sizes, int n_in,
                              void* d_out, int out_size) {
    const float* xg_old = (const float*)d_in[0];
    const float* x      = (const float*)d_in[1];
    const void*  batch  = d_in[2];
    const float* W_gate = (const float*)d_in[3];
    const float* b_gate = (const float*)d_in[4];
    const float* W_feat = (const float*)d_in[5];
    const float* b_feat = (const float*)d_in[6];
    const float* W_t    = (const float*)d_in[7];
    const float* b_t    = (const float*)d_in[8];
    float*       out    = (float*)d_out;

    int n = in_sizes[2];
    int b = in_sizes[0] / D;
    if (n > N_MAX) n = N_MAX;
    if (b > B_MAX) b = B_MAX;

    cudaFuncSetAttribute(k_main_mma, cudaFuncAttributeMaxDynamicSharedMemorySize,
                         SMEM_MAIN);

    k_detect<<<1, 1>>>(batch, n);
    k_seg<<<(n + 255) / 256, 256>>>(batch, n, b);
    k_gate<<<(n + 7) / 8, 256>>>(x, W_gate, b_gate, n);
    k_alpha<<<(b + 7) / 8, 256>>>(b);
    k_zero<<<(b * (D / 4) + 255) / 256, 256>>>(b * (D / 4));

    // n-block fastest -> both column blocks of the same rows run adjacently
    // (second read of x hits L2)
    dim3 gm(D / 128, (n + 127) / 128);
    k_main_mma<<<gm, 256, SMEM_MAIN>>>(x, W_feat, b_feat, n);

    dim3 gf((b + BM - 1) / BM, D / BN);
    k_final<<<gf, 256>>>(xg_old, W_t, b_t, out, b);
}

// round 8
// speedup vs baseline: 1.4933x; 1.2570x over previous
#include <cuda_runtime.h>
#include <cuda_fp16.h>
#include <math.h>
#include <stdint.h>

#define N_MAX 500000
#define B_MAX 10000
#define D 256

// ---------------- scratch (static device globals; no runtime alloc) --------
__device__ float g_gate[N_MAX];
__device__ float g_alpha[N_MAX];
__device__ int   g_batch32[N_MAX];
__device__ int   g_segstart[B_MAX + 1];
__device__ float g_xg[(size_t)B_MAX * D];
__device__ int   g_is64;
__device__ __half g_xhi[(size_t)N_MAX * D];
__device__ __half g_xlo[(size_t)N_MAX * D];
__device__ __half g_WhiT[D * D];   // [n][k]
__device__ __half g_WloT[D * D];   // [n][k]

// ---------------- helpers ----------------------------------------------------
__device__ __forceinline__ uint32_t smem_u32(const void* p) {
    uint32_t a;
    asm("{ .reg .u64 t; cvta.to.shared.u64 t, %1; cvt.u32.u64 %0, t; }"
        : "=r"(a) : "l"(p));
    return a;
}

#define LDSM_X4(r0, r1, r2, r3, addr) \
    asm volatile("ldmatrix.sync.aligned.m8n8.x4.shared.b16 {%0,%1,%2,%3}, [%4];" \
                 : "=r"(r0), "=r"(r1), "=r"(r2), "=r"(r3) : "r"(addr))

#define MMA16816(c0, c1, c2, c3, a0, a1, a2, a3, b0, b1) \
    asm volatile("mma.sync.aligned.m16n8k16.row.col.f32.f16.f16.f32 " \
                 "{%0,%1,%2,%3}, {%4,%5,%6,%7}, {%8,%9}, {%0,%1,%2,%3};" \
                 : "+f"(c0), "+f"(c1), "+f"(c2), "+f"(c3) \
                 : "r"(a0), "r"(a1), "r"(a2), "r"(a3), "r"(b0), "r"(b1))

#define CP16(dst, src) \
    asm volatile("cp.async.cg.shared.global [%0], [%1], 16;" \
                 :: "r"(dst), "l"(src) : "memory")
#define CP_COMMIT() asm volatile("cp.async.commit_group;" ::: "memory")
#define CP_WAIT(nn)  asm volatile("cp.async.wait_group %0;" :: "n"(nn) : "memory")

__device__ __forceinline__ uint32_t pack_hi2(float x, float y) {
    __half2 h = __halves2half2(__float2half_rn(x), __float2half_rn(y));
    return *(uint32_t*)&h;
}
__device__ __forceinline__ uint32_t pack_lo2(float x, float y, uint32_t hi) {
    __half2 h = *(__half2*)&hi;
    float2 f = __half22float2(h);
    __half2 l = __halves2half2(__float2half_rn(x - f.x), __float2half_rn(y - f.y));
    return *(uint32_t*)&l;
}

// ---------------- dtype detection for batch (int32 vs int64) ----------------
__global__ void k_detect(const void* __restrict__ batch, int n) {
    const unsigned long long* p = (const unsigned long long*)batch;
    unsigned long long v = 0;
    int half = n / 2;
    v |= p[half - 1];
    v |= p[half / 2];
    v |= p[half / 4];
    g_is64 = (v < 0x80000000ull) ? 1 : 0;
}

// ---------------- segment boundaries from sorted batch ----------------------
__global__ void k_seg(const void* __restrict__ batch, int n, int b) {
    int i = blockIdx.x * blockDim.x + threadIdx.x;
    if (i >= n) return;
    const int is64 = g_is64;
    int bi, prev;
    if (is64) {
        bi = (int)((const long long*)batch)[i];
        prev = (i == 0) ? -1 : (int)((const long long*)batch)[i - 1];
    } else {
        bi = ((const int*)batch)[i];
        prev = (i == 0) ? -1 : ((const int*)batch)[i - 1];
    }
    if (bi < 0) bi = 0;
    if (bi > b - 1) bi = b - 1;
    if (prev < -1) prev = -1;
    if (prev > b - 1) prev = b - 1;
    g_batch32[i] = bi;
    for (int bb = prev + 1; bb <= bi; ++bb) g_segstart[bb] = i;
    if (i == n - 1) {
        for (int bb = bi + 1; bb <= b; ++bb) g_segstart[bb] = n;
    }
}

// -------- gate = x @ W_gate + b_gate, fused with x -> (hi,lo) fp16 ----------
__global__ void k_gate(const float* __restrict__ x, const float* __restrict__ Wg,
                       const float* __restrict__ bg, int n) {
    int warp = (blockIdx.x * blockDim.x + threadIdx.x) >> 5;
    int lane = threadIdx.x & 31;
    if (warp >= n) return;
    const float4* xr = (const float4*)(x + (size_t)warp * D);
    const float4* wr = (const float4*)Wg;
    uint2* hr = (uint2*)(g_xhi + (size_t)warp * D);
    uint2* lr = (uint2*)(g_xlo + (size_t)warp * D);
    float acc = 0.f;
#pragma unroll
    for (int i = 0; i < 2; i++) {
        float4 a = xr[lane + 32 * i];
        float4 w = wr[lane + 32 * i];
        acc += a.x * w.x + a.y * w.y + a.z * w.z + a.w * w.w;
        uint32_t h0 = pack_hi2(a.x, a.y), h1 = pack_hi2(a.z, a.w);
        uint32_t l0 = pack_lo2(a.x, a.y, h0), l1 = pack_lo2(a.z, a.w, h1);
        hr[lane + 32 * i] = make_uint2(h0, h1);
        lr[lane + 32 * i] = make_uint2(l0, l1);
    }
#pragma unroll
    for (int o = 16; o; o >>= 1) acc += __shfl_xor_sync(0xffffffffu, acc, o);
    if (lane == 0) g_gate[warp] = acc + bg[0];
}

// ---------------- W_feat -> transposed hi/lo fp16 ---------------------------
__global__ void k_convW(const float* __restrict__ Wf) {
    int t = blockIdx.x * blockDim.x + threadIdx.x;
    if (t >= D * D) return;
    int nn = t >> 8, kk = t & 255;
    float v = Wf[kk * D + nn];
    uint32_t h = pack_hi2(v, 0.f);
    uint32_t l = pack_lo2(v, 0.f, h);
    g_WhiT[nn * D + kk] = *(__half*)&h;
    g_WloT[nn * D + kk] = *(__half*)&l;
}

// ---------------- per-graph softmax weights (warp per graph) ----------------
__global__ void k_alpha(int b) {
    int w = (blockIdx.x * blockDim.x + threadIdx.x) >> 5;
    int lane = threadIdx.x & 31;
    if (w >= b) return;
    int s = g_segstart[w], e = g_segstart[w + 1];
    if (s >= e) return;
    float m = -1e30f;
    for (int i = s + lane; i < e; i += 32) m = fmaxf(m, g_gate[i]);
#pragma unroll
    for (int o = 16; o; o >>= 1) m = fmaxf(m, __shfl_xor_sync(0xffffffffu, m, o));
    float sum = 0.f;
    for (int i = s + lane; i < e; i += 32) sum += expf(g_gate[i] - m);
#pragma unroll
    for (int o = 16; o; o >>= 1) sum += __shfl_xor_sync(0xffffffffu, sum, o);
    float inv = 1.0f / sum;
    for (int i = s + lane; i < e; i += 32) g_alpha[i] = expf(g_gate[i] - m) * inv;
}

// ---------------- zero xg accumulator ---------------------------------------
__global__ void k_zero(int total4) {
    int i = blockIdx.x * blockDim.x + threadIdx.x;
    if (i < total4) ((float4*)g_xg)[i] = make_float4(0.f, 0.f, 0.f, 0.f);
}

// ============ pipelined fp16 GEMM: xg += alpha * lrelu(x @ W_feat + b) ======
// CTA 128x128, 512 threads. B (hi+lo, full K=256) resident in smem.
// A streamed in 4 chunks of K=64 through 2 cp.async stages.
#define LDKB 144     // A row stride bytes (64 halfs + pad)
#define LDNB 528     // B row stride bytes (256 halfs + pad)
#define OFF_BHI 0
#define OFF_BLO 67584
#define OFF_A0  135168
#define A_ST    18432        // one A (hi or lo) buffer
#define A_STAGE 36864        // hi+lo
#define OFF_BATCH 208896
#define OFF_ALPHA 209408
#define OFF_BIAS  209920
#define SMEM_MAIN 210432
#define SD_STRIDE 130

__global__ void __launch_bounds__(512, 1)
k_main_mma(const float* __restrict__ bf, int n) {
    extern __shared__ char smem[];
    const int tid = threadIdx.x;
    const int m0 = blockIdx.y * 128;
    const int n0 = blockIdx.x * 128;
    const uint32_t sbase = smem_u32(smem);
    int*   sBatch = (int*)(smem + OFF_BATCH);
    float* sAlpha = (float*)(smem + OFF_ALPHA);
    float* sBias  = (float*)(smem + OFF_BIAS);
    float* sD     = (float*)smem;   // reused after compute (128 x 130 fp32)

    if (tid < 128) {
        int r = m0 + tid;
        sBatch[tid] = (r < n) ? g_batch32[r] : -1;
        sBias[tid]  = bf[n0 + tid];
    } else if (tid < 256) {
        int r = m0 + tid - 128;
        sAlpha[tid - 128] = (r < n) ? g_alpha[r] : 0.f;
    }

    // ---- copy mappings (512 threads) ----
    const int crow = tid >> 2;          // 0..127
    const int cseg = tid & 3;           // base 16B segment

    const char* whiT = (const char*)g_WhiT;
    const char* wloT = (const char*)g_WloT;
    const char* xhi  = (const char*)g_xhi;
    const char* xlo  = (const char*)g_xlo;

    // B resident: row = n-local, 32 segs of 16B per row per (hi/lo)
    {
        const size_t bsrc = ((size_t)(n0 + crow)) * 512;  // 256 halfs = 512B
        const uint32_t bdst = sbase + crow * LDNB;
#pragma unroll
        for (int j = 0; j < 8; j++) {
            int s = cseg + 4 * j;
            CP16(bdst + OFF_BHI + s * 16, whiT + bsrc + s * 16);
            CP16(bdst + OFF_BLO + s * 16, wloT + bsrc + s * 16);
        }
    }
    // A chunk copy helper (rows 128, 8 segs of 16B per row per hi/lo)
    const bool avalid = (m0 + crow) < n;
    const size_t asrc_row = ((size_t)(m0 + (avalid ? crow : 0))) * 512;

    // stage A chunk 0 (group 0 with B), chunk 1 (group 1)
#pragma unroll
    for (int st = 0; st < 2; st++) {
        const uint32_t adst = sbase + OFF_A0 + st * A_STAGE + crow * LDKB;
        const size_t asrc = asrc_row + st * 128;   // chunk k-offset bytes
        if (avalid) {
#pragma unroll
            for (int j = 0; j < 2; j++) {
                int s = cseg + 4 * j;
                CP16(adst + s * 16, xhi + asrc + s * 16);
                CP16(adst + A_ST + s * 16, xlo + asrc + s * 16);
            }
        } else {
#pragma unroll
            for (int j = 0; j < 2; j++) {
                int s = cseg + 4 * j;
                asm volatile("st.shared.v4.b32 [%0], {%1,%1,%1,%1};"
                             :: "r"(adst + s * 16), "r"(0u));
                asm volatile("st.shared.v4.b32 [%0], {%1,%1,%1,%1};"
                             :: "r"(adst + A_ST + s * 16), "r"(0u));
            }
        }
        CP_COMMIT();
    }
    CP_WAIT(1);
    __syncthreads();

    // ---- warp tiling: 4x4 warps, warp tile 32x32 ----
    const int wid = tid >> 5, lane = tid & 31;
    const int wm = wid >> 2, wn = wid & 3;
    const uint32_t a_off = (uint32_t)((wm * 32 + (lane & 15)) * LDKB + ((lane >> 4) << 4));
    const uint32_t b_off = (uint32_t)((wn * 32 + (lane & 15)) * LDNB + ((lane >> 4) << 4));

    float c[2][4][4];
#pragma unroll
    for (int mi = 0; mi < 2; mi++)
#pragma unroll
        for (int nt = 0; nt < 4; nt++)
#pragma unroll
            for (int q = 0; q < 4; q++) c[mi][nt][q] = 0.f;

    for (int ch = 0; ch < 4; ch++) {
        const int st = ch & 1;
        const uint32_t aH = sbase + OFF_A0 + st * A_STAGE + a_off;
        const uint32_t aL = aH + A_ST;
        const uint32_t bH = sbase + OFF_BHI + b_off + (uint32_t)(ch * 128);
        const uint32_t bL = bH + OFF_BLO;
#pragma unroll
        for (int ks = 0; ks < 4; ks++) {
            const uint32_t koff = (uint32_t)(ks * 32);
            uint32_t ah[2][4], al[2][4], bh[2][4], bl[2][4];
#pragma unroll
            for (int mi = 0; mi < 2; mi++) {
                uint32_t adr = aH + (uint32_t)(mi * 16 * LDKB) + koff;
                LDSM_X4(ah[mi][0], ah[mi][1], ah[mi][2], ah[mi][3], adr);
                uint32_t adr2 = aL + (uint32_t)(mi * 16 * LDKB) + koff;
                LDSM_X4(al[mi][0], al[mi][1], al[mi][2], al[mi][3], adr2);
            }
#pragma unroll
            for (int np = 0; np < 2; np++) {
                uint32_t adr = bH + (uint32_t)(np * 16 * LDNB) + koff;
                LDSM_X4(bh[np][0], bh[np][1], bh[np][2], bh[np][3], adr);
                uint32_t adr2 = bL + (uint32_t)(np * 16 * LDNB) + koff;
                LDSM_X4(bl[np][0], bl[np][1], bl[np][2], bl[np][3], adr2);
            }
#pragma unroll
            for (int mi = 0; mi < 2; mi++)
#pragma unroll
                for (int np = 0; np < 2; np++)
#pragma unroll
                    for (int t = 0; t < 2; t++) {
                        float* cc = c[mi][np * 2 + t];
                        MMA16816(cc[0], cc[1], cc[2], cc[3],
                                 ah[mi][0], ah[mi][1], ah[mi][2], ah[mi][3],
                                 bh[np][t], bh[np][t + 2]);
                        MMA16816(cc[0], cc[1], cc[2], cc[3],
                                 al[mi][0], al[mi][1], al[mi][2], al[mi][3],
                                 bh[np][t], bh[np][t + 2]);
                        MMA16816(cc[0], cc[1], cc[2], cc[3],
                                 ah[mi][0], ah[mi][1], ah[mi][2], ah[mi][3],
                                 bl[np][t], bl[np][t + 2]);
                    }
        }
        __syncthreads();   // done reading stage st

        if (ch + 2 < 4) {  // refill stage st with chunk ch+2
            const uint32_t adst = sbase + OFF_A0 + st * A_STAGE + crow * LDKB;
            const size_t asrc = asrc_row + (ch + 2) * 128;
            if (avalid) {
#pragma unroll
                for (int j = 0; j < 2; j++) {
                    int s = cseg + 4 * j;
                    CP16(adst + s * 16, xhi + asrc + s * 16);
                    CP16(adst + A_ST + s * 16, xlo + asrc + s * 16);
                }
            }
            CP_COMMIT();
        }
        if (ch == 0 || ch == 1) {
            CP_WAIT(1);
            __syncthreads();
        } else if (ch == 2) {
            CP_WAIT(0);
            __syncthreads();
        }
    }

    // ---- epilogue: bias + lrelu + alpha -> sD ----
#pragma unroll
    for (int mi = 0; mi < 2; mi++) {
        const int r0 = wm * 32 + mi * 16 + (lane >> 2);
        const int r1 = r0 + 8;
        const float al0 = sAlpha[r0], al1 = sAlpha[r1];
#pragma unroll
        for (int nt = 0; nt < 4; nt++) {
            const int col = wn * 32 + nt * 8 + (lane & 3) * 2;
            const float b0 = sBias[col], b1 = sBias[col + 1];
            float v0 = c[mi][nt][0] + b0, v1 = c[mi][nt][1] + b1;
            float v2 = c[mi][nt][2] + b0, v3 = c[mi][nt][3] + b1;
            v0 = (v0 >= 0.f) ? v0 : 0.01f * v0;
            v1 = (v1 >= 0.f) ? v1 : 0.01f * v1;
            v2 = (v2 >= 0.f) ? v2 : 0.01f * v2;
            v3 = (v3 >= 0.f) ? v3 : 0.01f * v3;
            *(float2*)&sD[r0 * SD_STRIDE + col] = make_float2(v0 * al0, v1 * al0);
            *(float2*)&sD[r1 * SD_STRIDE + col] = make_float2(v2 * al1, v3 * al1);
        }
    }
    __syncthreads();

    // ---- run-length compressed segment reduction + atomics ----
    {
        const int col = tid & 127, q = tid >> 7;   // 4 quarters of 32 rows
        const int rbeg = q * 32;
        float sum = 0.f;
        int prevb = -2;
        for (int r = 0; r < 32; r++) {
            int rr = rbeg + r;
            int b = sBatch[rr];
            if (b != prevb) {
                if (prevb >= 0)
                    atomicAdd(&g_xg[(size_t)prevb * D + n0 + col], sum);
                sum = 0.f;
                prevb = b;
            }
            if (b >= 0) sum += sD[rr * SD_STRIDE + col];
        }
        if (prevb >= 0) atomicAdd(&g_xg[(size_t)prevb * D + n0 + col], sum);
    }
}

// ---------------- final: out = lrelu([xg | xg_old] @ W_t + b_t) + xg_old ----
#define BM 128
#define BN 128
#define BK 16
#define BMP 132
#define TM 8
#define TN 8

__global__ void __launch_bounds__(256) k_final(const float* __restrict__ xg_old,
                                               const float* __restrict__ Wt,
                                               const float* __restrict__ bt,
                                               float* __restrict__ out, int bsz) {
    __shared__ float As[2][BK * BMP];
    __shared__ float Bs[2][BK * BN];

    const int tid = threadIdx.x;
    const int tx = tid & 15;
    const int ty = tid >> 4;
    const int m0 = blockIdx.x * BM;
    const int n0 = blockIdx.y * BN;

    const int a_r = tid >> 2;
    const int a_k = (tid & 3) * 4;
    const int b_k = tid >> 5;
    const int b_c = (tid & 31) * 4;

    float acc[TM][TN];
#pragma unroll
    for (int i = 0; i < TM; i++)
#pragma unroll
        for (int j = 0; j < TN; j++) acc[i][j] = 0.f;

    const int K2 = 2 * D;
    const int NST = K2 / BK;
    float4 va[2], vb[2];

    auto loadA = [&](int gr, int c) -> float4 {
        if (gr >= bsz) return make_float4(0.f, 0.f, 0.f, 0.f);
        if (c < D) return *(const float4*)(g_xg + (size_t)gr * D + c);
        return *(const float4*)(xg_old + (size_t)gr * D + (c - D));
    };

#pragma unroll
    for (int i = 0; i < 2; i++) {
        va[i] = loadA(m0 + a_r + 64 * i, a_k);
        vb[i] = *(const float4*)(Wt + (size_t)(b_k + 8 * i) * D + n0 + b_c);
    }
    int buf = 0;
#pragma unroll
    for (int i = 0; i < 2; i++) {
        int r = a_r + 64 * i;
        As[buf][(a_k + 0) * BMP + r] = va[i].x;
        As[buf][(a_k + 1) * BMP + r] = va[i].y;
        As[buf][(a_k + 2) * BMP + r] = va[i].z;
        As[buf][(a_k + 3) * BMP + r] = va[i].w;
        *(float4*)&Bs[buf][(b_k + 8 * i) * BN + b_c] = vb[i];
    }
    __syncthreads();

    for (int t = 0; t < NST; ++t) {
        if (t + 1 < NST) {
            int kk = (t + 1) * BK;
#pragma unroll
            for (int i = 0; i < 2; i++) {
                va[i] = loadA(m0 + a_r + 64 * i, kk + a_k);
                vb[i] = *(const float4*)(Wt + (size_t)(kk + b_k + 8 * i) * D + n0 + b_c);
            }
        }
        float ra[TM], rb[TN];
#pragma unroll
        for (int k = 0; k < BK; k++) {
            *(float4*)&ra[0] = *(float4*)&As[buf][k * BMP + ty * 8];
            *(float4*)&ra[4] = *(float4*)&As[buf][k * BMP + ty * 8 + 4];
            *(float4*)&rb[0] = *(float4*)&Bs[buf][k * BN + tx * 8];
            *(float4*)&rb[4] = *(float4*)&Bs[buf][k * BN + tx * 8 + 4];
#pragma unroll
            for (int i = 0; i < TM; i++)
#pragma unroll
                for (int j = 0; j < TN; j++) acc[i][j] += ra[i] * rb[j];
        }
        if (t + 1 < NST) {
            int nb = buf ^ 1;
#pragma unroll
            for (int i = 0; i < 2; i++) {
                int r = a_r + 64 * i;
                As[nb][(a_k + 0) * BMP + r] = va[i].x;
                As[nb][(a_k + 1) * BMP + r] = va[i].y;
                As[nb][(a_k + 2) * BMP + r] = va[i].z;
                As[nb][(a_k + 3) * BMP + r] = va[i].w;
                *(float4*)&Bs[nb][(b_k + 8 * i) * BN + b_c] = vb[i];
            }
        }
        __syncthreads();
        buf ^= 1;
    }

    const int col0 = n0 + tx * 8;
    float bias[TN];
    *(float4*)&bias[0] = *(const float4*)(bt + col0);
    *(float4*)&bias[4] = *(const float4*)(bt + col0 + 4);

#pragma unroll
    for (int i = 0; i < TM; i++) {
        int gr = m0 + ty * 8 + i;
        if (gr >= bsz) continue;
        float res[TN];
        *(float4*)&res[0] = *(const float4*)(xg_old + (size_t)gr * D + col0);
        *(float4*)&res[4] = *(const float4*)(xg_old + (size_t)gr * D + col0 + 4);
        float o[TN];
#pragma unroll
        for (int j = 0; j < TN; j++) {
            float v = acc[i][j] + bias[j];
            v = (v >= 0.f) ? v : 0.01f * v;
            o[j] = v + res[j];
        }
        *(float4*)(out + (size_t)gr * D + col0) = *(float4*)&o[0];
        *(float4*)(out + (size_t)gr * D + col0 + 4) = *(float4*)&o[4];
    }
}

// ---------------- launcher ---------------------------------------------------
extern "C" void kernel_launch(void* const* d_in, const int* in_sizes, int n_in,
                              void* d_out, int out_size) {
    const float* xg_old = (const float*)d_in[0];
    const float* x      = (const float*)d_in[1];
    const void*  batch  = d_in[2];
    const float* W_gate = (const float*)d_in[3];
    const float* b_gate = (const float*)d_in[4];
    const float* W_feat = (const float*)d_in[5];
    const float* b_feat = (const float*)d_in[6];
    const float* W_t    = (const float*)d_in[7];
    const float* b_t    = (const float*)d_in[8];
    float*       out    = (float*)d_out;

    int n = in_sizes[2];
    int b = in_sizes[0] / D;
    if (n > N_MAX) n = N_MAX;
    if (b > B_MAX) b = B_MAX;

    cudaFuncSetAttribute(k_main_mma, cudaFuncAttributeMaxDynamicSharedMemorySize,
                         SMEM_MAIN);

    k_detect<<<1, 1>>>(batch, n);
    k_seg<<<(n + 255) / 256, 256>>>(batch, n, b);
    k_convW<<<(D * D + 255) / 256, 256>>>(W_feat);
    k_gate<<<(n + 7) / 8, 256>>>(x, W_gate, b_gate, n);
    k_alpha<<<(b + 7) / 8, 256>>>(b);
    k_zero<<<(b * (D / 4) + 255) / 256, 256>>>(b * (D / 4));

    // n-block fastest -> both column blocks of same rows adjacent (L2 reuse)
    dim3 gm(D / 128, (n + 127) / 128);
    k_main_mma<<<gm, 512, SMEM_MAIN>>>(b_feat, n);

    dim3 gf((b + BM - 1) / BM, D / BN);
    k_final<<<gf, 256>>>(xg_old, W_t, b_t, out, b);
}

// round 11
// speedup vs baseline: 2.0110x; 1.3467x over previous
#include <cuda_runtime.h>
#include <cuda_fp16.h>
#include <math.h>
#include <stdint.h>

#define N_MAX 500000
#define B_MAX 10000
#define D 256

// ---------------- scratch (static device globals; no runtime alloc) --------
__device__ float g_gate[N_MAX];
__device__ float g_alpha[N_MAX];
__device__ int   g_batch32[N_MAX];
__device__ int   g_segstart[B_MAX + 1];
__device__ float g_xg[(size_t)B_MAX * D];
__device__ int   g_is64;
__device__ __half g_xhi[(size_t)N_MAX * D];
__device__ __half g_WhiT[D * D];   // [n][k]
__device__ __half g_WloT[D * D];   // [n][k]

// ---------------- helpers ----------------------------------------------------
__device__ __forceinline__ uint32_t smem_u32(const void* p) {
    uint32_t a;
    asm("{ .reg .u64 t; cvta.to.shared.u64 t, %1; cvt.u32.u64 %0, t; }"
        : "=r"(a) : "l"(p));
    return a;
}

#define LDSM_X4(r0, r1, r2, r3, addr) \
    asm volatile("ldmatrix.sync.aligned.m8n8.x4.shared.b16 {%0,%1,%2,%3}, [%4];" \
                 : "=r"(r0), "=r"(r1), "=r"(r2), "=r"(r3) : "r"(addr))

#define MMA16816(c0, c1, c2, c3, a0, a1, a2, a3, b0, b1) \
    asm volatile("mma.sync.aligned.m16n8k16.row.col.f32.f16.f16.f32 " \
                 "{%0,%1,%2,%3}, {%4,%5,%6,%7}, {%8,%9}, {%0,%1,%2,%3};" \
                 : "+f"(c0), "+f"(c1), "+f"(c2), "+f"(c3) \
                 : "r"(a0), "r"(a1), "r"(a2), "r"(a3), "r"(b0), "r"(b1))

#define CP16(dst, src) \
    asm volatile("cp.async.cg.shared.global [%0], [%1], 16;" \
                 :: "r"(dst), "l"(src) : "memory")
#define CP_COMMIT() asm volatile("cp.async.commit_group;" ::: "memory")
#define CP_WAIT(nn)  asm volatile("cp.async.wait_group %0;" :: "n"(nn) : "memory")

__device__ __forceinline__ uint32_t pack_hi2(float x, float y) {
    __half2 h = __halves2half2(__float2half_rn(x), __float2half_rn(y));
    return *(uint32_t*)&h;
}
__device__ __forceinline__ uint32_t pack_lo2(float x, float y, uint32_t hi) {
    __half2 h = *(__half2*)&hi;
    float2 f = __half22float2(h);
    __half2 l = __halves2half2(__float2half_rn(x - f.x), __float2half_rn(y - f.y));
    return *(uint32_t*)&l;
}

// ---------------- dtype detection for batch (int32 vs int64) ----------------
__global__ void k_detect(const void* __restrict__ batch, int n) {
    const unsigned long long* p = (const unsigned long long*)batch;
    unsigned long long v = 0;
    int half = n / 2;
    v |= p[half - 1];
    v |= p[half / 2];
    v |= p[half / 4];
    g_is64 = (v < 0x80000000ull) ? 1 : 0;
}

// ---------------- segment boundaries from sorted batch ----------------------
__global__ void k_seg(const void* __restrict__ batch, int n, int b) {
    int i = blockIdx.x * blockDim.x + threadIdx.x;
    if (i >= n) return;
    const int is64 = g_is64;
    int bi, prev;
    if (is64) {
        bi = (int)((const long long*)batch)[i];
        prev = (i == 0) ? -1 : (int)((const long long*)batch)[i - 1];
    } else {
        bi = ((const int*)batch)[i];
        prev = (i == 0) ? -1 : ((const int*)batch)[i - 1];
    }
    if (bi < 0) bi = 0;
    if (bi > b - 1) bi = b - 1;
    if (prev < -1) prev = -1;
    if (prev > b - 1) prev = b - 1;
    g_batch32[i] = bi;
    for (int bb = prev + 1; bb <= bi; ++bb) g_segstart[bb] = i;
    if (i == n - 1) {
        for (int bb = bi + 1; bb <= b; ++bb) g_segstart[bb] = n;
    }
}

// -------- gate = x @ W_gate + b_gate, fused with x -> fp16 ------------------
__global__ void k_gate(const float* __restrict__ x, const float* __restrict__ Wg,
                       const float* __restrict__ bg, int n) {
    int warp = (blockIdx.x * blockDim.x + threadIdx.x) >> 5;
    int lane = threadIdx.x & 31;
    if (warp >= n) return;
    const float4* xr = (const float4*)(x + (size_t)warp * D);
    const float4* wr = (const float4*)Wg;
    uint2* hr = (uint2*)(g_xhi + (size_t)warp * D);
    float acc = 0.f;
#pragma unroll
    for (int i = 0; i < 2; i++) {
        float4 a = xr[lane + 32 * i];
        float4 w = wr[lane + 32 * i];
        acc += a.x * w.x + a.y * w.y + a.z * w.z + a.w * w.w;
        uint32_t h0 = pack_hi2(a.x, a.y), h1 = pack_hi2(a.z, a.w);
        hr[lane + 32 * i] = make_uint2(h0, h1);
    }
#pragma unroll
    for (int o = 16; o; o >>= 1) acc += __shfl_xor_sync(0xffffffffu, acc, o);
    if (lane == 0) g_gate[warp] = acc + bg[0];
}

// ---------------- W_feat -> transposed hi/lo fp16 ---------------------------
__global__ void k_convW(const float* __restrict__ Wf) {
    int t = blockIdx.x * blockDim.x + threadIdx.x;
    if (t >= D * D) return;
    int nn = t >> 8, kk = t & 255;
    float v = Wf[kk * D + nn];
    uint32_t h = pack_hi2(v, 0.f);
    uint32_t l = pack_lo2(v, 0.f, h);
    g_WhiT[nn * D + kk] = *(__half*)&h;
    g_WloT[nn * D + kk] = *(__half*)&l;
}

// ---------------- per-graph softmax weights (warp per graph) ----------------
__global__ void k_alpha(int b) {
    int w = (blockIdx.x * blockDim.x + threadIdx.x) >> 5;
    int lane = threadIdx.x & 31;
    if (w >= b) return;
    int s = g_segstart[w], e = g_segstart[w + 1];
    if (s >= e) return;
    float m = -1e30f;
    for (int i = s + lane; i < e; i += 32) m = fmaxf(m, g_gate[i]);
#pragma unroll
    for (int o = 16; o; o >>= 1) m = fmaxf(m, __shfl_xor_sync(0xffffffffu, m, o));
    float sum = 0.f;
    for (int i = s + lane; i < e; i += 32) sum += expf(g_gate[i] - m);
#pragma unroll
    for (int o = 16; o; o >>= 1) sum += __shfl_xor_sync(0xffffffffu, sum, o);
    float inv = 1.0f / sum;
    for (int i = s + lane; i < e; i += 32) g_alpha[i] = expf(g_gate[i] - m) * inv;
}

// ---------------- zero xg accumulator ---------------------------------------
__global__ void k_zero(int total4) {
    int i = blockIdx.x * blockDim.x + threadIdx.x;
    if (i < total4) ((float4*)g_xg)[i] = make_float4(0.f, 0.f, 0.f, 0.f);
}

// ======= 2-term fp16 GEMM: xg += alpha * lrelu(xhi @ (Whi+Wlo) + b) =========
// CTA 128x128, 512 threads. B (Whi+Wlo, full K=256) resident in smem.
// A (xhi only) streamed in 4 chunks of K=64 through 2 cp.async stages.
#define LDKB 144     // A row stride bytes (64 halfs + pad)
#define LDNB 528     // B row stride bytes (256 halfs + pad)
#define OFF_BHI 0
#define OFF_BLO 67584
#define OFF_A0  135168
#define A_STAGE 18432
#define OFF_BATCH 172032
#define OFF_ALPHA 172544
#define OFF_BIAS  173056
#define SMEM_MAIN 173568
#define SD_STRIDE 130

__global__ void __launch_bounds__(512, 1)
k_main_mma(const float* __restrict__ bf, int n) {
    extern __shared__ char smem[];
    const int tid = threadIdx.x;
    const int m0 = blockIdx.y * 128;
    const int n0 = blockIdx.x * 128;
    const uint32_t sbase = smem_u32(smem);
    int*   sBatch = (int*)(smem + OFF_BATCH);
    float* sAlpha = (float*)(smem + OFF_ALPHA);
    float* sBias  = (float*)(smem + OFF_BIAS);
    float* sD     = (float*)smem;   // reused after compute (128 x 130 fp32)

    if (tid < 128) {
        int r = m0 + tid;
        sBatch[tid] = (r < n) ? g_batch32[r] : -1;
        sBias[tid]  = bf[n0 + tid];
    } else if (tid < 256) {
        int r = m0 + tid - 128;
        sAlpha[tid - 128] = (r < n) ? g_alpha[r] : 0.f;
    }

    // ---- copy mappings (512 threads) ----
    const int crow = tid >> 2;          // 0..127
    const int cseg = tid & 3;           // base 16B segment

    const char* whiT = (const char*)g_WhiT;
    const char* wloT = (const char*)g_WloT;
    const char* xhi  = (const char*)g_xhi;

    // B resident: row = n-local, 32 segs of 16B per row per (hi/lo)
    {
        const size_t bsrc = ((size_t)(n0 + crow)) * 512;  // 256 halfs = 512B
        const uint32_t bdst = sbase + crow * LDNB;
#pragma unroll
        for (int j = 0; j < 8; j++) {
            int s = cseg + 4 * j;
            CP16(bdst + OFF_BHI + s * 16, whiT + bsrc + s * 16);
            CP16(bdst + OFF_BLO + s * 16, wloT + bsrc + s * 16);
        }
    }
    const bool avalid = (m0 + crow) < n;
    const size_t asrc_row = ((size_t)(m0 + (avalid ? crow : 0))) * 512;

    // stage A chunk 0 (group 0 with B), chunk 1 (group 1)
#pragma unroll
    for (int st = 0; st < 2; st++) {
        const uint32_t adst = sbase + OFF_A0 + st * A_STAGE + crow * LDKB;
        const size_t asrc = asrc_row + st * 128;   // chunk k-offset bytes
        if (avalid) {
#pragma unroll
            for (int j = 0; j < 2; j++) {
                int s = cseg + 4 * j;
                CP16(adst + s * 16, xhi + asrc + s * 16);
            }
        } else {
#pragma unroll
            for (int j = 0; j < 2; j++) {
                int s = cseg + 4 * j;
                asm volatile("st.shared.v4.b32 [%0], {%1,%1,%1,%1};"
                             :: "r"(adst + s * 16), "r"(0u));
            }
        }
        CP_COMMIT();
    }
    CP_WAIT(1);
    __syncthreads();

    // ---- warp tiling: 4x4 warps, warp tile 32x32 ----
    const int wid = tid >> 5, lane = tid & 31;
    const int wm = wid >> 2, wn = wid & 3;
    const uint32_t a_off = (uint32_t)((wm * 32 + (lane & 15)) * LDKB + ((lane >> 4) << 4));
    const uint32_t b_off = (uint32_t)((wn * 32 + (lane & 15)) * LDNB + ((lane >> 4) << 4));

    float c[2][4][4];
#pragma unroll
    for (int mi = 0; mi < 2; mi++)
#pragma unroll
        for (int nt = 0; nt < 4; nt++)
#pragma unroll
            for (int q = 0; q < 4; q++) c[mi][nt][q] = 0.f;

    for (int ch = 0; ch < 4; ch++) {
        const int st = ch & 1;
        const uint32_t aH = sbase + OFF_A0 + st * A_STAGE + a_off;
        const uint32_t bH = sbase + OFF_BHI + b_off + (uint32_t)(ch * 128);
        const uint32_t bL = bH + OFF_BLO;
#pragma unroll
        for (int ks = 0; ks < 4; ks++) {
            const uint32_t koff = (uint32_t)(ks * 32);
            uint32_t ah[2][4], bh[2][4], bl[2][4];
#pragma unroll
            for (int mi = 0; mi < 2; mi++) {
                uint32_t adr = aH + (uint32_t)(mi * 16 * LDKB) + koff;
                LDSM_X4(ah[mi][0], ah[mi][1], ah[mi][2], ah[mi][3], adr);
            }
#pragma unroll
            for (int np = 0; np < 2; np++) {
                uint32_t adr = bH + (uint32_t)(np * 16 * LDNB) + koff;
                LDSM_X4(bh[np][0], bh[np][1], bh[np][2], bh[np][3], adr);
                uint32_t adr2 = bL + (uint32_t)(np * 16 * LDNB) + koff;
                LDSM_X4(bl[np][0], bl[np][1], bl[np][2], bl[np][3], adr2);
            }
#pragma unroll
            for (int mi = 0; mi < 2; mi++)
#pragma unroll
                for (int np = 0; np < 2; np++)
#pragma unroll
                    for (int t = 0; t < 2; t++) {
                        float* cc = c[mi][np * 2 + t];
                        MMA16816(cc[0], cc[1], cc[2], cc[3],
                                 ah[mi][0], ah[mi][1], ah[mi][2], ah[mi][3],
                                 bh[np][t], bh[np][t + 2]);
                        MMA16816(cc[0], cc[1], cc[2], cc[3],
                                 ah[mi][0], ah[mi][1], ah[mi][2], ah[mi][3],
                                 bl[np][t], bl[np][t + 2]);
                    }
        }
        __syncthreads();   // done reading stage st

        if (ch + 2 < 4) {  // refill stage st with chunk ch+2
            const uint32_t adst = sbase + OFF_A0 + st * A_STAGE + crow * LDKB;
            const size_t asrc = asrc_row + (ch + 2) * 128;
            if (avalid) {
#pragma unroll
                for (int j = 0; j < 2; j++) {
                    int s = cseg + 4 * j;
                    CP16(adst + s * 16, xhi + asrc + s * 16);
                }
            }
            CP_COMMIT();
        }
        if (ch == 0 || ch == 1) {
            CP_WAIT(1);
            __syncthreads();
        } else if (ch == 2) {
            CP_WAIT(0);
            __syncthreads();
        }
    }

    // ---- epilogue: bias + lrelu + alpha -> sD ----
#pragma unroll
    for (int mi = 0; mi < 2; mi++) {
        const int r0 = wm * 32 + mi * 16 + (lane >> 2);
        const int r1 = r0 + 8;
        const float al0 = sAlpha[r0], al1 = sAlpha[r1];
#pragma unroll
        for (int nt = 0; nt < 4; nt++) {
            const int col = wn * 32 + nt * 8 + (lane & 3) * 2;
            const float b0 = sBias[col], b1 = sBias[col + 1];
            float v0 = c[mi][nt][0] + b0, v1 = c[mi][nt][1] + b1;
            float v2 = c[mi][nt][2] + b0, v3 = c[mi][nt][3] + b1;
            v0 = (v0 >= 0.f) ? v0 : 0.01f * v0;
            v1 = (v1 >= 0.f) ? v1 : 0.01f * v1;
            v2 = (v2 >= 0.f) ? v2 : 0.01f * v2;
            v3 = (v3 >= 0.f) ? v3 : 0.01f * v3;
            *(float2*)&sD[r0 * SD_STRIDE + col] = make_float2(v0 * al0, v1 * al0);
            *(float2*)&sD[r1 * SD_STRIDE + col] = make_float2(v2 * al1, v3 * al1);
        }
    }
    __syncthreads();

    // ---- run-length compressed segment reduction + atomics ----
    {
        const int col = tid & 127, q = tid >> 7;   // 4 quarters of 32 rows
        const int rbeg = q * 32;
        float sum = 0.f;
        int prevb = -2;
        for (int r = 0; r < 32; r++) {
            int rr = rbeg + r;
            int b = sBatch[rr];
            if (b != prevb) {
                if (prevb >= 0)
                    atomicAdd(&g_xg[(size_t)prevb * D + n0 + col], sum);
                sum = 0.f;
                prevb = b;
            }
            if (b >= 0) sum += sD[rr * SD_STRIDE + col];
        }
        if (prevb >= 0) atomicAdd(&g_xg[(size_t)prevb * D + n0 + col], sum);
    }
}

// ---------------- final: out = lrelu([xg | xg_old] @ W_t + b_t) + xg_old ----
#define BM 128
#define BN 128
#define BK 16
#define BMP 132
#define TM 8
#define TN 8

__global__ void __launch_bounds__(256) k_final(const float* __restrict__ xg_old,
                                               const float* __restrict__ Wt,
                                               const float* __restrict__ bt,
                                               float* __restrict__ out, int bsz) {
    __shared__ float As[2][BK * BMP];
    __shared__ float Bs[2][BK * BN];

    const int tid = threadIdx.x;
    const int tx = tid & 15;
    const int ty = tid >> 4;
    const int m0 = blockIdx.x * BM;
    const int n0 = blockIdx.y * BN;

    const int a_r = tid >> 2;
    const int a_k = (tid & 3) * 4;
    const int b_k = tid >> 5;
    const int b_c = (tid & 31) * 4;

    float acc[TM][TN];
#pragma unroll
    for (int i = 0; i < TM; i++)
#pragma unroll
        for (int j = 0; j < TN; j++) acc[i][j] = 0.f;

    const int K2 = 2 * D;
    const int NST = K2 / BK;
    float4 va[2], vb[2];

    auto loadA = [&](int gr, int c) -> float4 {
        if (gr >= bsz) return make_float4(0.f, 0.f, 0.f, 0.f);
        if (c < D) return *(const float4*)(g_xg + (size_t)gr * D + c);
        return *(const float4*)(xg_old + (size_t)gr * D + (c - D));
    };

#pragma unroll
    for (int i = 0; i < 2; i++) {
        va[i] = loadA(m0 + a_r + 64 * i, a_k);
        vb[i] = *(const float4*)(Wt + (size_t)(b_k + 8 * i) * D + n0 + b_c);
    }
    int buf = 0;
#pragma unroll
    for (int i = 0; i < 2; i++) {
        int r = a_r + 64 * i;
        As[buf][(a_k + 0) * BMP + r] = va[i].x;
        As[buf][(a_k + 1) * BMP + r] = va[i].y;
        As[buf][(a_k + 2) * BMP + r] = va[i].z;
        As[buf][(a_k + 3) * BMP + r] = va[i].w;
        *(float4*)&Bs[buf][(b_k + 8 * i) * BN + b_c] = vb[i];
    }
    __syncthreads();

    for (int t = 0; t < NST; ++t) {
        if (t + 1 < NST) {
            int kk = (t + 1) * BK;
#pragma unroll
            for (int i = 0; i < 2; i++) {
                va[i] = loadA(m0 + a_r + 64 * i, kk + a_k);
                vb[i] = *(const float4*)(Wt + (size_t)(kk + b_k + 8 * i) * D + n0 + b_c);
            }
        }
        float ra[TM], rb[TN];
#pragma unroll
        for (int k = 0; k < BK; k++) {
            *(float4*)&ra[0] = *(float4*)&As[buf][k * BMP + ty * 8];
            *(float4*)&ra[4] = *(float4*)&As[buf][k * BMP + ty * 8 + 4];
            *(float4*)&rb[0] = *(float4*)&Bs[buf][k * BN + tx * 8];
            *(float4*)&rb[4] = *(float4*)&Bs[buf][k * BN + tx * 8 + 4];
#pragma unroll
            for (int i = 0; i < TM; i++)
#pragma unroll
                for (int j = 0; j < TN; j++) acc[i][j] += ra[i] * rb[j];
        }
        if (t + 1 < NST) {
            int nb = buf ^ 1;
#pragma unroll
            for (int i = 0; i < 2; i++) {
                int r = a_r + 64 * i;
                As[nb][(a_k + 0) * BMP + r] = va[i].x;
                As[nb][(a_k + 1) * BMP + r] = va[i].y;
                As[nb][(a_k + 2) * BMP + r] = va[i].z;
                As[nb][(a_k + 3) * BMP + r] = va[i].w;
                *(float4*)&Bs[nb][(b_k + 8 * i) * BN + b_c] = vb[i];
            }
        }
        __syncthreads();
        buf ^= 1;
    }

    const int col0 = n0 + tx * 8;
    float bias[TN];
    *(float4*)&bias[0] = *(const float4*)(bt + col0);
    *(float4*)&bias[4] = *(const float4*)(bt + col0 + 4);

#pragma unroll
    for (int i = 0; i < TM; i++) {
        int gr = m0 + ty * 8 + i;
        if (gr >= bsz) continue;
        float res[TN];
        *(float4*)&res[0] = *(const float4*)(xg_old + (size_t)gr * D + col0);
        *(float4*)&res[4] = *(const float4*)(xg_old + (size_t)gr * D + col0 + 4);
        float o[TN];
#pragma unroll
        for (int j = 0; j < TN; j++) {
            float v = acc[i][j] + bias[j];
            v = (v >= 0.f) ? v : 0.01f * v;
            o[j] = v + res[j];
        }
        *(float4*)(out + (size_t)gr * D + col0) = *(float4*)&o[0];
        *(float4*)(out + (size_t)gr * D + col0 + 4) = *(float4*)&o[4];
    }
}

// ---------------- launcher ---------------------------------------------------
extern "C" void kernel_launch(void* const* d_in, const int* in_sizes, int n_in,
                              void* d_out, int out_size) {
    const float* xg_old = (const float*)d_in[0];
    const float* x      = (const float*)d_in[1];
    const void*  batch  = d_in[2];
    const float* W_gate = (const float*)d_in[3];
    const float* b_gate = (const float*)d_in[4];
    const float* W_feat = (const float*)d_in[5];
    const float* b_feat = (const float*)d_in[6];
    const float* W_t    = (const float*)d_in[7];
    const float* b_t    = (const float*)d_in[8];
    float*       out    = (float*)d_out;

    int n = in_sizes[2];
    int b = in_sizes[0] / D;
    if (n > N_MAX) n = N_MAX;
    if (b > B_MAX) b = B_MAX;

    cudaFuncSetAttribute(k_main_mma, cudaFuncAttributeMaxDynamicSharedMemorySize,
                         SMEM_MAIN);

    k_detect<<<1, 1>>>(batch, n);
    k_seg<<<(n + 255) / 256, 256>>>(batch, n, b);
    k_convW<<<(D * D + 255) / 256, 256>>>(W_feat);
    k_gate<<<(n + 7) / 8, 256>>>(x, W_gate, b_gate, n);
    k_alpha<<<(b + 7) / 8, 256>>>(b);
    k_zero<<<(b * (D / 4) + 255) / 256, 256>>>(b * (D / 4));

    // n-block fastest -> both column blocks of same rows adjacent (L2 reuse)
    dim3 gm(D / 128, (n + 127) / 128);
    k_main_mma<<<gm, 512, SMEM_MAIN>>>(b_feat, n);

    dim3 gf((b + BM - 1) / BM, D / BN);
    k_final<<<gf, 256>>>(xg_old, W_t, b_t, out, b);
}

// round 12
// speedup vs baseline: 3.0504x; 1.5169x over previous
#include <cuda_runtime.h>
#include <cuda_fp16.h>
#include <math.h>
#include <stdint.h>

#define N_MAX 500000
#define B_MAX 10000
#define D 256

// ---------------- scratch (static device globals; no runtime alloc) --------
__device__ float g_gate[N_MAX];
__device__ float g_alpha[N_MAX];
__device__ int   g_batch32[N_MAX];
__device__ int   g_segstart[B_MAX + 1];
__device__ float g_xg[(size_t)B_MAX * D];
__device__ int   g_is64;
__device__ __half g_xhi[(size_t)N_MAX * D];
__device__ __half g_WhiT[D * D];   // [n][k]

// ---------------- helpers ----------------------------------------------------
__device__ __forceinline__ uint32_t smem_u32(const void* p) {
    uint32_t a;
    asm("{ .reg .u64 t; cvta.to.shared.u64 t, %1; cvt.u32.u64 %0, t; }"
        : "=r"(a) : "l"(p));
    return a;
}

#define LDSM_X4(r0, r1, r2, r3, addr) \
    asm volatile("ldmatrix.sync.aligned.m8n8.x4.shared.b16 {%0,%1,%2,%3}, [%4];" \
                 : "=r"(r0), "=r"(r1), "=r"(r2), "=r"(r3) : "r"(addr))

#define MMA16816(c0, c1, c2, c3, a0, a1, a2, a3, b0, b1) \
    asm volatile("mma.sync.aligned.m16n8k16.row.col.f32.f16.f16.f32 " \
                 "{%0,%1,%2,%3}, {%4,%5,%6,%7}, {%8,%9}, {%0,%1,%2,%3};" \
                 : "+f"(c0), "+f"(c1), "+f"(c2), "+f"(c3) \
                 : "r"(a0), "r"(a1), "r"(a2), "r"(a3), "r"(b0), "r"(b1))

#define CP16(dst, src) \
    asm volatile("cp.async.cg.shared.global [%0], [%1], 16;" \
                 :: "r"(dst), "l"(src) : "memory")
#define CP_COMMIT() asm volatile("cp.async.commit_group;" ::: "memory")
#define CP_WAIT(nn)  asm volatile("cp.async.wait_group %0;" :: "n"(nn) : "memory")

__device__ __forceinline__ uint32_t pack_hi2(float x, float y) {
    __half2 h = __halves2half2(__float2half_rn(x), __float2half_rn(y));
    return *(uint32_t*)&h;
}

// ---------------- dtype detection for batch (int32 vs int64) ----------------
__global__ void k_detect(const void* __restrict__ batch, int n) {
    const unsigned long long* p = (const unsigned long long*)batch;
    unsigned long long v = 0;
    int half = n / 2;
    v |= p[half - 1];
    v |= p[half / 2];
    v |= p[half / 4];
    g_is64 = (v < 0x80000000ull) ? 1 : 0;
}

// ---------------- segment boundaries from sorted batch ----------------------
__global__ void k_seg(const void* __restrict__ batch, int n, int b) {
    int i = blockIdx.x * blockDim.x + threadIdx.x;
    if (i >= n) return;
    const int is64 = g_is64;
    int bi, prev;
    if (is64) {
        bi = (int)((const long long*)batch)[i];
        prev = (i == 0) ? -1 : (int)((const long long*)batch)[i - 1];
    } else {
        bi = ((const int*)batch)[i];
        prev = (i == 0) ? -1 : ((const int*)batch)[i - 1];
    }
    if (bi < 0) bi = 0;
    if (bi > b - 1) bi = b - 1;
    if (prev < -1) prev = -1;
    if (prev > b - 1) prev = b - 1;
    g_batch32[i] = bi;
    for (int bb = prev + 1; bb <= bi; ++bb) g_segstart[bb] = i;
    if (i == n - 1) {
        for (int bb = bi + 1; bb <= b; ++bb) g_segstart[bb] = n;
    }
}

// -------- gate = x @ W_gate + b_gate, fused with x -> fp16 ------------------
__global__ void k_gate(const float* __restrict__ x, const float* __restrict__ Wg,
                       const float* __restrict__ bg, int n) {
    int warp = (blockIdx.x * blockDim.x + threadIdx.x) >> 5;
    int lane = threadIdx.x & 31;
    if (warp >= n) return;
    const float4* xr = (const float4*)(x + (size_t)warp * D);
    const float4* wr = (const float4*)Wg;
    uint2* hr = (uint2*)(g_xhi + (size_t)warp * D);
    float acc = 0.f;
#pragma unroll
    for (int i = 0; i < 2; i++) {
        float4 a = xr[lane + 32 * i];
        float4 w = wr[lane + 32 * i];
        acc += a.x * w.x + a.y * w.y + a.z * w.z + a.w * w.w;
        uint32_t h0 = pack_hi2(a.x, a.y), h1 = pack_hi2(a.z, a.w);
        hr[lane + 32 * i] = make_uint2(h0, h1);
    }
#pragma unroll
    for (int o = 16; o; o >>= 1) acc += __shfl_xor_sync(0xffffffffu, acc, o);
    if (lane == 0) g_gate[warp] = acc + bg[0];
}

// ---------------- W_feat -> transposed fp16 ---------------------------------
__global__ void k_convW(const float* __restrict__ Wf) {
    int t = blockIdx.x * blockDim.x + threadIdx.x;
    if (t >= D * D) return;
    int nn = t >> 8, kk = t & 255;
    g_WhiT[nn * D + kk] = __float2half_rn(Wf[kk * D + nn]);
}

// ---------------- per-graph softmax weights (warp per graph) ----------------
__global__ void k_alpha(int b) {
    int w = (blockIdx.x * blockDim.x + threadIdx.x) >> 5;
    int lane = threadIdx.x & 31;
    if (w >= b) return;
    int s = g_segstart[w], e = g_segstart[w + 1];
    if (s >= e) return;
    float m = -1e30f;
    for (int i = s + lane; i < e; i += 32) m = fmaxf(m, g_gate[i]);
#pragma unroll
    for (int o = 16; o; o >>= 1) m = fmaxf(m, __shfl_xor_sync(0xffffffffu, m, o));
    float sum = 0.f;
    for (int i = s + lane; i < e; i += 32) sum += expf(g_gate[i] - m);
#pragma unroll
    for (int o = 16; o; o >>= 1) sum += __shfl_xor_sync(0xffffffffu, sum, o);
    float inv = 1.0f / sum;
    for (int i = s + lane; i < e; i += 32) g_alpha[i] = expf(g_gate[i] - m) * inv;
}

// ---------------- zero xg accumulator ---------------------------------------
__global__ void k_zero(int total4) {
    int i = blockIdx.x * blockDim.x + threadIdx.x;
    if (i < total4) ((float4*)g_xg)[i] = make_float4(0.f, 0.f, 0.f, 0.f);
}

// ========= single-term fp16 GEMM: xg += alpha * lrelu(xhi @ Whi + b) ========
// CTA 128x128, 512 threads, 2 CTAs/SM. B (Whi, full K=256) resident in smem.
// A (xhi) streamed in 4 chunks of K=64 through 2 cp.async stages.
#define LDKB 144     // A row stride bytes (64 halfs + pad)
#define LDNB 528     // B row stride bytes (256 halfs + pad)
#define OFF_BHI 0
#define OFF_A0  67584
#define A_STAGE 18432
#define OFF_BATCH 104448
#define OFF_ALPHA 104960
#define OFF_BIAS  105472
#define SMEM_MAIN 105984
#define SD_STRIDE 130

__global__ void __launch_bounds__(512, 2)
k_main_mma(const float* __restrict__ bf, int n) {
    extern __shared__ char smem[];
    const int tid = threadIdx.x;
    const int m0 = blockIdx.y * 128;
    const int n0 = blockIdx.x * 128;
    const uint32_t sbase = smem_u32(smem);
    int*   sBatch = (int*)(smem + OFF_BATCH);
    float* sAlpha = (float*)(smem + OFF_ALPHA);
    float* sBias  = (float*)(smem + OFF_BIAS);
    float* sD     = (float*)smem;   // reused after compute (128 x 130 fp32)

    if (tid < 128) {
        int r = m0 + tid;
        sBatch[tid] = (r < n) ? g_batch32[r] : -1;
        sBias[tid]  = bf[n0 + tid];
    } else if (tid < 256) {
        int r = m0 + tid - 128;
        sAlpha[tid - 128] = (r < n) ? g_alpha[r] : 0.f;
    }

    // ---- copy mappings (512 threads) ----
    const int crow = tid >> 2;          // 0..127
    const int cseg = tid & 3;           // base 16B segment

    const char* whiT = (const char*)g_WhiT;
    const char* xhi  = (const char*)g_xhi;

    // B resident: row = n-local, 32 segs of 16B per row
    {
        const size_t bsrc = ((size_t)(n0 + crow)) * 512;  // 256 halfs = 512B
        const uint32_t bdst = sbase + crow * LDNB;
#pragma unroll
        for (int j = 0; j < 8; j++) {
            int s = cseg + 4 * j;
            CP16(bdst + OFF_BHI + s * 16, whiT + bsrc + s * 16);
        }
    }
    const bool avalid = (m0 + crow) < n;
    const size_t asrc_row = ((size_t)(m0 + (avalid ? crow : 0))) * 512;

    // stage A chunk 0 (group 0 with B), chunk 1 (group 1)
#pragma unroll
    for (int st = 0; st < 2; st++) {
        const uint32_t adst = sbase + OFF_A0 + st * A_STAGE + crow * LDKB;
        const size_t asrc = asrc_row + st * 128;   // chunk k-offset bytes
        if (avalid) {
#pragma unroll
            for (int j = 0; j < 2; j++) {
                int s = cseg + 4 * j;
                CP16(adst + s * 16, xhi + asrc + s * 16);
            }
        } else {
#pragma unroll
            for (int j = 0; j < 2; j++) {
                int s = cseg + 4 * j;
                asm volatile("st.shared.v4.b32 [%0], {%1,%1,%1,%1};"
                             :: "r"(adst + s * 16), "r"(0u));
            }
        }
        CP_COMMIT();
    }
    CP_WAIT(1);
    __syncthreads();

    // ---- warp tiling: 4x4 warps, warp tile 32x32 ----
    const int wid = tid >> 5, lane = tid & 31;
    const int wm = wid >> 2, wn = wid & 3;
    const uint32_t a_off = (uint32_t)((wm * 32 + (lane & 15)) * LDKB + ((lane >> 4) << 4));
    const uint32_t b_off = (uint32_t)((wn * 32 + (lane & 15)) * LDNB + ((lane >> 4) << 4));

    float c[2][4][4];
#pragma unroll
    for (int mi = 0; mi < 2; mi++)
#pragma unroll
        for (int nt = 0; nt < 4; nt++)
#pragma unroll
            for (int q = 0; q < 4; q++) c[mi][nt][q] = 0.f;

    for (int ch = 0; ch < 4; ch++) {
        const int st = ch & 1;
        const uint32_t aH = sbase + OFF_A0 + st * A_STAGE + a_off;
        const uint32_t bH = sbase + OFF_BHI + b_off + (uint32_t)(ch * 128);
#pragma unroll
        for (int ks = 0; ks < 4; ks++) {
            const uint32_t koff = (uint32_t)(ks * 32);
            uint32_t ah[2][4], bh[2][4];
#pragma unroll
            for (int mi = 0; mi < 2; mi++) {
                uint32_t adr = aH + (uint32_t)(mi * 16 * LDKB) + koff;
                LDSM_X4(ah[mi][0], ah[mi][1], ah[mi][2], ah[mi][3], adr);
            }
#pragma unroll
            for (int np = 0; np < 2; np++) {
                uint32_t adr = bH + (uint32_t)(np * 16 * LDNB) + koff;
                LDSM_X4(bh[np][0], bh[np][1], bh[np][2], bh[np][3], adr);
            }
#pragma unroll
            for (int mi = 0; mi < 2; mi++)
#pragma unroll
                for (int np = 0; np < 2; np++)
#pragma unroll
                    for (int t = 0; t < 2; t++) {
                        float* cc = c[mi][np * 2 + t];
                        MMA16816(cc[0], cc[1], cc[2], cc[3],
                                 ah[mi][0], ah[mi][1], ah[mi][2], ah[mi][3],
                                 bh[np][t], bh[np][t + 2]);
                    }
        }
        __syncthreads();   // done reading stage st

        if (ch + 2 < 4) {  // refill stage st with chunk ch+2
            const uint32_t adst = sbase + OFF_A0 + st * A_STAGE + crow * LDKB;
            const size_t asrc = asrc_row + (ch + 2) * 128;
            if (avalid) {
#pragma unroll
                for (int j = 0; j < 2; j++) {
                    int s = cseg + 4 * j;
                    CP16(adst + s * 16, xhi + asrc + s * 16);
                }
            }
            CP_COMMIT();
        }
        if (ch == 0 || ch == 1) {
            CP_WAIT(1);
            __syncthreads();
        } else if (ch == 2) {
            CP_WAIT(0);
            __syncthreads();
        }
    }

    // ---- epilogue: bias + lrelu + alpha -> sD ----
#pragma unroll
    for (int mi = 0; mi < 2; mi++) {
        const int r0 = wm * 32 + mi * 16 + (lane >> 2);
        const int r1 = r0 + 8;
        const float al0 = sAlpha[r0], al1 = sAlpha[r1];
#pragma unroll
        for (int nt = 0; nt < 4; nt++) {
            const int col = wn * 32 + nt * 8 + (lane & 3) * 2;
            const float b0 = sBias[col], b1 = sBias[col + 1];
            float v0 = c[mi][nt][0] + b0, v1 = c[mi][nt][1] + b1;
            float v2 = c[mi][nt][2] + b0, v3 = c[mi][nt][3] + b1;
            v0 = (v0 >= 0.f) ? v0 : 0.01f * v0;
            v1 = (v1 >= 0.f) ? v1 : 0.01f * v1;
            v2 = (v2 >= 0.f) ? v2 : 0.01f * v2;
            v3 = (v3 >= 0.f) ? v3 : 0.01f * v3;
            *(float2*)&sD[r0 * SD_STRIDE + col] = make_float2(v0 * al0, v1 * al0);
            *(float2*)&sD[r1 * SD_STRIDE + col] = make_float2(v2 * al1, v3 * al1);
        }
    }
    __syncthreads();

    // ---- run-length compressed segment reduction + atomics ----
    {
        const int col = tid & 127, q = tid >> 7;   // 4 quarters of 32 rows
        const int rbeg = q * 32;
        float sum = 0.f;
        int prevb = -2;
        for (int r = 0; r < 32; r++) {
            int rr = rbeg + r;
            int b = sBatch[rr];
            if (b != prevb) {
                if (prevb >= 0)
                    atomicAdd(&g_xg[(size_t)prevb * D + n0 + col], sum);
                sum = 0.f;
                prevb = b;
            }
            if (b >= 0) sum += sD[rr * SD_STRIDE + col];
        }
        if (prevb >= 0) atomicAdd(&g_xg[(size_t)prevb * D + n0 + col], sum);
    }
}

// ---------------- final: out = lrelu([xg | xg_old] @ W_t + b_t) + xg_old ----
#define BM 128
#define BN 128
#define BK 16
#define BMP 132
#define TM 8
#define TN 8

__global__ void __launch_bounds__(256) k_final(const float* __restrict__ xg_old,
                                               const float* __restrict__ Wt,
                                               const float* __restrict__ bt,
                                               float* __restrict__ out, int bsz) {
    __shared__ float As[2][BK * BMP];
    __shared__ float Bs[2][BK * BN];

    const int tid = threadIdx.x;
    const int tx = tid & 15;
    const int ty = tid >> 4;
    const int m0 = blockIdx.x * BM;
    const int n0 = blockIdx.y * BN;

    const int a_r = tid >> 2;
    const int a_k = (tid & 3) * 4;
    const int b_k = tid >> 5;
    const int b_c = (tid & 31) * 4;

    float acc[TM][TN];
#pragma unroll
    for (int i = 0; i < TM; i++)
#pragma unroll
        for (int j = 0; j < TN; j++) acc[i][j] = 0.f;

    const int K2 = 2 * D;
    const int NST = K2 / BK;
    float4 va[2], vb[2];

    auto loadA = [&](int gr, int c) -> float4 {
        if (gr >= bsz) return make_float4(0.f, 0.f, 0.f, 0.f);
        if (c < D) return *(const float4*)(g_xg + (size_t)gr * D + c);
        return *(const float4*)(xg_old + (size_t)gr * D + (c - D));
    };

#pragma unroll
    for (int i = 0; i < 2; i++) {
        va[i] = loadA(m0 + a_r + 64 * i, a_k);
        vb[i] = *(const float4*)(Wt + (size_t)(b_k + 8 * i) * D + n0 + b_c);
    }
    int buf = 0;
#pragma unroll
    for (int i = 0; i < 2; i++) {
        int r = a_r + 64 * i;
        As[buf][(a_k + 0) * BMP + r] = va[i].x;
        As[buf][(a_k + 1) * BMP + r] = va[i].y;
        As[buf][(a_k + 2) * BMP + r] = va[i].z;
        As[buf][(a_k + 3) * BMP + r] = va[i].w;
        *(float4*)&Bs[buf][(b_k + 8 * i) * BN + b_c] = vb[i];
    }
    __syncthreads();

    for (int t = 0; t < NST; ++t) {
        if (t + 1 < NST) {
            int kk = (t + 1) * BK;
#pragma unroll
            for (int i = 0; i < 2; i++) {
                va[i] = loadA(m0 + a_r + 64 * i, kk + a_k);
                vb[i] = *(const float4*)(Wt + (size_t)(kk + b_k + 8 * i) * D + n0 + b_c);
            }
        }
        float ra[TM], rb[TN];
#pragma unroll
        for (int k = 0; k < BK; k++) {
            *(float4*)&ra[0] = *(float4*)&As[buf][k * BMP + ty * 8];
            *(float4*)&ra[4] = *(float4*)&As[buf][k * BMP + ty * 8 + 4];
            *(float4*)&rb[0] = *(float4*)&Bs[buf][k * BN + tx * 8];
            *(float4*)&rb[4] = *(float4*)&Bs[buf][k * BN + tx * 8 + 4];
#pragma unroll
            for (int i = 0; i < TM; i++)
#pragma unroll
                for (int j = 0; j < TN; j++) acc[i][j] += ra[i] * rb[j];
        }
        if (t + 1 < NST) {
            int nb = buf ^ 1;
#pragma unroll
            for (int i = 0; i < 2; i++) {
                int r = a_r + 64 * i;
                As[nb][(a_k + 0) * BMP + r] = va[i].x;
                As[nb][(a_k + 1) * BMP + r] = va[i].y;
                As[nb][(a_k + 2) * BMP + r] = va[i].z;
                As[nb][(a_k + 3) * BMP + r] = va[i].w;
                *(float4*)&Bs[nb][(b_k + 8 * i) * BN + b_c] = vb[i];
            }
        }
        __syncthreads();
        buf ^= 1;
    }

    const int col0 = n0 + tx * 8;
    float bias[TN];
    *(float4*)&bias[0] = *(const float4*)(bt + col0);
    *(float4*)&bias[4] = *(const float4*)(bt + col0 + 4);

#pragma unroll
    for (int i = 0; i < TM; i++) {
        int gr = m0 + ty * 8 + i;
        if (gr >= bsz) continue;
        float res[TN];
        *(float4*)&res[0] = *(const float4*)(xg_old + (size_t)gr * D + col0);
        *(float4*)&res[4] = *(const float4*)(xg_old + (size_t)gr * D + col0 + 4);
        float o[TN];
#pragma unroll
        for (int j = 0; j < TN; j++) {
            float v = acc[i][j] + bias[j];
            v = (v >= 0.f) ? v : 0.01f * v;
            o[j] = v + res[j];
        }
        *(float4*)(out + (size_t)gr * D + col0) = *(float4*)&o[0];
        *(float4*)(out + (size_t)gr * D + col0 + 4) = *(float4*)&o[4];
    }
}

// ---------------- launcher ---------------------------------------------------
extern "C" void kernel_launch(void* const* d_in, const int* in_sizes, int n_in,
                              void* d_out, int out_size) {
    const float* xg_old = (const float*)d_in[0];
    const float* x      = (const float*)d_in[1];
    const void*  batch  = d_in[2];
    const float* W_gate = (const float*)d_in[3];
    const float* b_gate = (const float*)d_in[4];
    const float* W_feat = (const float*)d_in[5];
    const float* b_feat = (const float*)d_in[6];
    const float* W_t    = (const float*)d_in[7];
    const float* b_t    = (const float*)d_in[8];
    float*       out    = (float*)d_out;

    int n = in_sizes[2];
    int b = in_sizes[0] / D;
    if (n > N_MAX) n = N_MAX;
    if (b > B_MAX) b = B_MAX;

    cudaFuncSetAttribute(k_main_mma, cudaFuncAttributeMaxDynamicSharedMemorySize,
                         SMEM_MAIN);

    k_detect<<<1, 1>>>(batch, n);
    k_seg<<<(n + 255) / 256, 256>>>(batch, n, b);
    k_convW<<<(D * D + 255) / 256, 256>>>(W_feat);
    k_gate<<<(n + 7) / 8, 256>>>(x, W_gate, b_gate, n);
    k_alpha<<<(b + 7) / 8, 256>>>(b);
    k_zero<<<(b * (D / 4) + 255) / 256, 256>>>(b * (D / 4));

    // n-block fastest -> both column blocks of same rows adjacent (L2 reuse)
    dim3 gm(D / 128, (n + 127) / 128);
    k_main_mma<<<gm, 512, SMEM_MAIN>>>(b_feat, n);

    dim3 gf((b + BM - 1) / BM, D / BN);
    k_final<<<gf, 256>>>(xg_old, W_t, b_t, out, b);
}

// round 13
// speedup vs baseline: 3.4514x; 1.1314x over previous
#include <cuda_runtime.h>
#include <cuda_fp16.h>
#include <math.h>
#include <stdint.h>

#define N_MAX 500000
#define B_MAX 10000
#define D 256

// ---------------- scratch (static device globals; no runtime alloc) --------
__device__ float g_gate[N_MAX];
__device__ float g_alpha[N_MAX];
__device__ int   g_batch32[N_MAX];
__device__ int   g_segstart[B_MAX + 1];
__device__ float g_xg[(size_t)B_MAX * D];
__device__ int   g_is64;
__device__ __half g_xhi[(size_t)N_MAX * D];
__device__ __half g_WhiT[D * D];              // [n][k]
__device__ __half g_catA[(size_t)B_MAX * 2 * D];   // [g][ xg | xg_old ] fp16
__device__ __half g_WtT[2 * D * D];           // [n][k2] fp16, k2 = 512

// ---------------- helpers ----------------------------------------------------
__device__ __forceinline__ uint32_t smem_u32(const void* p) {
    uint32_t a;
    asm("{ .reg .u64 t; cvta.to.shared.u64 t, %1; cvt.u32.u64 %0, t; }"
        : "=r"(a) : "l"(p));
    return a;
}

#define LDSM_X4(r0, r1, r2, r3, addr) \
    asm volatile("ldmatrix.sync.aligned.m8n8.x4.shared.b16 {%0,%1,%2,%3}, [%4];" \
                 : "=r"(r0), "=r"(r1), "=r"(r2), "=r"(r3) : "r"(addr))

#define MMA16816(c0, c1, c2, c3, a0, a1, a2, a3, b0, b1) \
    asm volatile("mma.sync.aligned.m16n8k16.row.col.f32.f16.f16.f32 " \
                 "{%0,%1,%2,%3}, {%4,%5,%6,%7}, {%8,%9}, {%0,%1,%2,%3};" \
                 : "+f"(c0), "+f"(c1), "+f"(c2), "+f"(c3) \
                 : "r"(a0), "r"(a1), "r"(a2), "r"(a3), "r"(b0), "r"(b1))

#define CP16(dst, src) \
    asm volatile("cp.async.cg.shared.global [%0], [%1], 16;" \
                 :: "r"(dst), "l"(src) : "memory")
#define CP_COMMIT() asm volatile("cp.async.commit_group;" ::: "memory")
#define CP_WAIT(nn)  asm volatile("cp.async.wait_group %0;" :: "n"(nn) : "memory")

__device__ __forceinline__ uint32_t pack_hi2(float x, float y) {
    __half2 h = __halves2half2(__float2half_rn(x), __float2half_rn(y));
    return *(uint32_t*)&h;
}

// ---------------- dtype detection for batch (int32 vs int64) ----------------
__global__ void k_detect(const void* __restrict__ batch, int n) {
    const unsigned long long* p = (const unsigned long long*)batch;
    unsigned long long v = 0;
    int half = n / 2;
    v |= p[half - 1];
    v |= p[half / 2];
    v |= p[half / 4];
    g_is64 = (v < 0x80000000ull) ? 1 : 0;
}

// ---------------- segment boundaries from sorted batch ----------------------
__global__ void k_seg(const void* __restrict__ batch, int n, int b) {
    int i = blockIdx.x * blockDim.x + threadIdx.x;
    if (i >= n) return;
    const int is64 = g_is64;
    int bi, prev;
    if (is64) {
        bi = (int)((const long long*)batch)[i];
        prev = (i == 0) ? -1 : (int)((const long long*)batch)[i - 1];
    } else {
        bi = ((const int*)batch)[i];
        prev = (i == 0) ? -1 : ((const int*)batch)[i - 1];
    }
    if (bi < 0) bi = 0;
    if (bi > b - 1) bi = b - 1;
    if (prev < -1) prev = -1;
    if (prev > b - 1) prev = b - 1;
    g_batch32[i] = bi;
    for (int bb = prev + 1; bb <= bi; ++bb) g_segstart[bb] = i;
    if (i == n - 1) {
        for (int bb = bi + 1; bb <= b; ++bb) g_segstart[bb] = n;
    }
}

// -------- gate = x @ W_gate + b_gate, fused with x -> fp16 (16B stores) -----
__global__ void k_gate(const float* __restrict__ x, const float* __restrict__ Wg,
                       const float* __restrict__ bg, int n) {
    int warp = (blockIdx.x * blockDim.x + threadIdx.x) >> 5;
    int lane = threadIdx.x & 31;
    if (warp >= n) return;
    const float4* xr = (const float4*)(x + (size_t)warp * D);
    const float4* wr = (const float4*)Wg;
    uint4* hr = (uint4*)(g_xhi + (size_t)warp * D);
    float4 a0 = xr[2 * lane], a1 = xr[2 * lane + 1];
    float4 w0 = wr[2 * lane], w1 = wr[2 * lane + 1];
    float acc = a0.x * w0.x + a0.y * w0.y + a0.z * w0.z + a0.w * w0.w +
                a1.x * w1.x + a1.y * w1.y + a1.z * w1.z + a1.w * w1.w;
    uint4 h;
    h.x = pack_hi2(a0.x, a0.y);
    h.y = pack_hi2(a0.z, a0.w);
    h.z = pack_hi2(a1.x, a1.y);
    h.w = pack_hi2(a1.z, a1.w);
    hr[lane] = h;
#pragma unroll
    for (int o = 16; o; o >>= 1) acc += __shfl_xor_sync(0xffffffffu, acc, o);
    if (lane == 0) g_gate[warp] = acc + bg[0];
}

// ---------------- W_feat -> transposed fp16 ---------------------------------
__global__ void k_convW(const float* __restrict__ Wf) {
    int t = blockIdx.x * blockDim.x + threadIdx.x;
    if (t >= D * D) return;
    int nn = t >> 8, kk = t & 255;
    g_WhiT[nn * D + kk] = __float2half_rn(Wf[kk * D + nn]);
}

// ---------------- W_t -> transposed fp16 [256 n][512 k] ---------------------
__global__ void k_convWt(const float* __restrict__ Wt) {
    int t = blockIdx.x * blockDim.x + threadIdx.x;
    if (t >= 2 * D * D) return;
    int k2 = t >> 8, nn = t & 255;
    g_WtT[nn * 2 * D + k2] = __float2half_rn(Wt[k2 * D + nn]);
}

// ---------------- [xg | xg_old] -> fp16 packed A ----------------------------
__global__ void k_convA(const float* __restrict__ xg_old, int b) {
    int t = blockIdx.x * blockDim.x + threadIdx.x;
    if (t >= b * D) return;
    int g = t >> 8, c = t & 255;
    g_catA[(size_t)g * 512 + c]       = __float2half_rn(g_xg[(size_t)g * D + c]);
    g_catA[(size_t)g * 512 + 256 + c] = __float2half_rn(xg_old[(size_t)g * D + c]);
}

// ---------------- per-graph softmax weights (warp per graph) ----------------
__global__ void k_alpha(int b) {
    int w = (blockIdx.x * blockDim.x + threadIdx.x) >> 5;
    int lane = threadIdx.x & 31;
    if (w >= b) return;
    int s = g_segstart[w], e = g_segstart[w + 1];
    if (s >= e) return;
    float m = -1e30f;
    for (int i = s + lane; i < e; i += 32) m = fmaxf(m, g_gate[i]);
#pragma unroll
    for (int o = 16; o; o >>= 1) m = fmaxf(m, __shfl_xor_sync(0xffffffffu, m, o));
    float sum = 0.f;
    for (int i = s + lane; i < e; i += 32) sum += expf(g_gate[i] - m);
#pragma unroll
    for (int o = 16; o; o >>= 1) sum += __shfl_xor_sync(0xffffffffu, sum, o);
    float inv = 1.0f / sum;
    for (int i = s + lane; i < e; i += 32) g_alpha[i] = expf(g_gate[i] - m) * inv;
}

// ---------------- zero xg accumulator ---------------------------------------
__global__ void k_zero(int total4) {
    int i = blockIdx.x * blockDim.x + threadIdx.x;
    if (i < total4) ((float4*)g_xg)[i] = make_float4(0.f, 0.f, 0.f, 0.f);
}

// ========= single-term fp16 GEMM: xg += alpha * lrelu(xhi @ Whi + b) ========
#define LDKB 144     // A row stride bytes (64 halfs + pad)
#define LDNB 528     // B row stride bytes (256 halfs + pad)
#define OFF_BHI 0
#define OFF_A0  67584
#define A_STAGE 18432
#define OFF_BATCH 104448
#define OFF_ALPHA 104960
#define OFF_BIAS  105472
#define SMEM_MAIN 105984
#define SD_STRIDE 130

__global__ void __launch_bounds__(512, 2)
k_main_mma(const float* __restrict__ bf, int n) {
    extern __shared__ char smem[];
    const int tid = threadIdx.x;
    const int m0 = blockIdx.y * 128;
    const int n0 = blockIdx.x * 128;
    const uint32_t sbase = smem_u32(smem);
    int*   sBatch = (int*)(smem + OFF_BATCH);
    float* sAlpha = (float*)(smem + OFF_ALPHA);
    float* sBias  = (float*)(smem + OFF_BIAS);
    float* sD     = (float*)smem;

    if (tid < 128) {
        int r = m0 + tid;
        sBatch[tid] = (r < n) ? g_batch32[r] : -1;
        sBias[tid]  = bf[n0 + tid];
    } else if (tid < 256) {
        int r = m0 + tid - 128;
        sAlpha[tid - 128] = (r < n) ? g_alpha[r] : 0.f;
    }

    const int crow = tid >> 2;
    const int cseg = tid & 3;
    const char* whiT = (const char*)g_WhiT;
    const char* xhi  = (const char*)g_xhi;

    {
        const size_t bsrc = ((size_t)(n0 + crow)) * 512;
        const uint32_t bdst = sbase + crow * LDNB;
#pragma unroll
        for (int j = 0; j < 8; j++) {
            int s = cseg + 4 * j;
            CP16(bdst + OFF_BHI + s * 16, whiT + bsrc + s * 16);
        }
    }
    const bool avalid = (m0 + crow) < n;
    const size_t asrc_row = ((size_t)(m0 + (avalid ? crow : 0))) * 512;

#pragma unroll
    for (int st = 0; st < 2; st++) {
        const uint32_t adst = sbase + OFF_A0 + st * A_STAGE + crow * LDKB;
        const size_t asrc = asrc_row + st * 128;
        if (avalid) {
#pragma unroll
            for (int j = 0; j < 2; j++) {
                int s = cseg + 4 * j;
                CP16(adst + s * 16, xhi + asrc + s * 16);
            }
        } else {
#pragma unroll
            for (int j = 0; j < 2; j++) {
                int s = cseg + 4 * j;
                asm volatile("st.shared.v4.b32 [%0], {%1,%1,%1,%1};"
                             :: "r"(adst + s * 16), "r"(0u));
            }
        }
        CP_COMMIT();
    }
    CP_WAIT(1);
    __syncthreads();

    const int wid = tid >> 5, lane = tid & 31;
    const int wm = wid >> 2, wn = wid & 3;
    const uint32_t a_off = (uint32_t)((wm * 32 + (lane & 15)) * LDKB + ((lane >> 4) << 4));
    const uint32_t b_off = (uint32_t)((wn * 32 + (lane & 15)) * LDNB + ((lane >> 4) << 4));

    float c[2][4][4];
#pragma unroll
    for (int mi = 0; mi < 2; mi++)
#pragma unroll
        for (int nt = 0; nt < 4; nt++)
#pragma unroll
            for (int q = 0; q < 4; q++) c[mi][nt][q] = 0.f;

    for (int ch = 0; ch < 4; ch++) {
        const int st = ch & 1;
        const uint32_t aH = sbase + OFF_A0 + st * A_STAGE + a_off;
        const uint32_t bH = sbase + OFF_BHI + b_off + (uint32_t)(ch * 128);
#pragma unroll
        for (int ks = 0; ks < 4; ks++) {
            const uint32_t koff = (uint32_t)(ks * 32);
            uint32_t ah[2][4], bh[2][4];
#pragma unroll
            for (int mi = 0; mi < 2; mi++) {
                uint32_t adr = aH + (uint32_t)(mi * 16 * LDKB) + koff;
                LDSM_X4(ah[mi][0], ah[mi][1], ah[mi][2], ah[mi][3], adr);
            }
#pragma unroll
            for (int np = 0; np < 2; np++) {
                uint32_t adr = bH + (uint32_t)(np * 16 * LDNB) + koff;
                LDSM_X4(bh[np][0], bh[np][1], bh[np][2], bh[np][3], adr);
            }
#pragma unroll
            for (int mi = 0; mi < 2; mi++)
#pragma unroll
                for (int np = 0; np < 2; np++)
#pragma unroll
                    for (int t = 0; t < 2; t++) {
                        float* cc = c[mi][np * 2 + t];
                        MMA16816(cc[0], cc[1], cc[2], cc[3],
                                 ah[mi][0], ah[mi][1], ah[mi][2], ah[mi][3],
                                 bh[np][t], bh[np][t + 2]);
                    }
        }
        __syncthreads();

        if (ch + 2 < 4) {
            const uint32_t adst = sbase + OFF_A0 + st * A_STAGE + crow * LDKB;
            const size_t asrc = asrc_row + (ch + 2) * 128;
            if (avalid) {
#pragma unroll
                for (int j = 0; j < 2; j++) {
                    int s = cseg + 4 * j;
                    CP16(adst + s * 16, xhi + asrc + s * 16);
                }
            }
            CP_COMMIT();
        }
        if (ch == 0 || ch == 1) {
            CP_WAIT(1);
            __syncthreads();
        } else if (ch == 2) {
            CP_WAIT(0);
            __syncthreads();
        }
    }

#pragma unroll
    for (int mi = 0; mi < 2; mi++) {
        const int r0 = wm * 32 + mi * 16 + (lane >> 2);
        const int r1 = r0 + 8;
        const float al0 = sAlpha[r0], al1 = sAlpha[r1];
#pragma unroll
        for (int nt = 0; nt < 4; nt++) {
            const int col = wn * 32 + nt * 8 + (lane & 3) * 2;
            const float b0 = sBias[col], b1 = sBias[col + 1];
            float v0 = c[mi][nt][0] + b0, v1 = c[mi][nt][1] + b1;
            float v2 = c[mi][nt][2] + b0, v3 = c[mi][nt][3] + b1;
            v0 = (v0 >= 0.f) ? v0 : 0.01f * v0;
            v1 = (v1 >= 0.f) ? v1 : 0.01f * v1;
            v2 = (v2 >= 0.f) ? v2 : 0.01f * v2;
            v3 = (v3 >= 0.f) ? v3 : 0.01f * v3;
            *(float2*)&sD[r0 * SD_STRIDE + col] = make_float2(v0 * al0, v1 * al0);
            *(float2*)&sD[r1 * SD_STRIDE + col] = make_float2(v2 * al1, v3 * al1);
        }
    }
    __syncthreads();

    {
        const int col = tid & 127, q = tid >> 7;
        const int rbeg = q * 32;
        float sum = 0.f;
        int prevb = -2;
        for (int r = 0; r < 32; r++) {
            int rr = rbeg + r;
            int b = sBatch[rr];
            if (b != prevb) {
                if (prevb >= 0)
                    atomicAdd(&g_xg[(size_t)prevb * D + n0 + col], sum);
                sum = 0.f;
                prevb = b;
            }
            if (b >= 0) sum += sD[rr * SD_STRIDE + col];
        }
        if (prevb >= 0) atomicAdd(&g_xg[(size_t)prevb * D + n0 + col], sum);
    }
}

// ===== fp16 final GEMM: out = lrelu([xg|xg_old] @ W_t + b_t) + xg_old =======
// CTA 128x128, 512 threads. B (W_t^T 128n x 512k fp16) resident; A streamed
// in 8 chunks of K=64 through 2 cp.async stages.
#define F_LDNB 1040             // 512 halfs + 16B pad
#define F_OFF_B 0
#define F_B_BYTES 133120        // 128 * 1040
#define F_OFF_A0 133120
#define F_A_STAGE 18432
#define F_OFF_BIAS 169984
#define SMEM_FIN   170496

__global__ void __launch_bounds__(512, 1)
k_final_mma(const float* __restrict__ xg_old, const float* __restrict__ bt,
            float* __restrict__ out, int bsz) {
    extern __shared__ char smem[];
    const int tid = threadIdx.x;
    const int m0 = blockIdx.y * 128;
    const int n0 = blockIdx.x * 128;
    const uint32_t sbase = smem_u32(smem);
    float* sBias = (float*)(smem + F_OFF_BIAS);

    if (tid < 128) sBias[tid] = bt[n0 + tid];

    const int crow = tid >> 2;
    const int cseg = tid & 3;
    const char* wt  = (const char*)g_WtT;
    const char* cat = (const char*)g_catA;

    // B resident: 128 rows(n) x 1024B (64 segs of 16B)
    {
        const size_t bsrc = ((size_t)(n0 + crow)) * 1024;
        const uint32_t bdst = sbase + F_OFF_B + crow * F_LDNB;
#pragma unroll
        for (int j = 0; j < 16; j++) {
            int s = cseg + 4 * j;
            CP16(bdst + s * 16, wt + bsrc + s * 16);
        }
    }
    const bool avalid = (m0 + crow) < bsz;
    const size_t asrc_row = ((size_t)(m0 + (avalid ? crow : 0))) * 1024;

#pragma unroll
    for (int st = 0; st < 2; st++) {
        const uint32_t adst = sbase + F_OFF_A0 + st * F_A_STAGE + crow * LDKB;
        const size_t asrc = asrc_row + st * 128;
        if (avalid) {
#pragma unroll
            for (int j = 0; j < 2; j++) {
                int s = cseg + 4 * j;
                CP16(adst + s * 16, cat + asrc + s * 16);
            }
        } else {
#pragma unroll
            for (int j = 0; j < 2; j++) {
                int s = cseg + 4 * j;
                asm volatile("st.shared.v4.b32 [%0], {%1,%1,%1,%1};"
                             :: "r"(adst + s * 16), "r"(0u));
            }
        }
        CP_COMMIT();
    }
    CP_WAIT(1);
    __syncthreads();

    const int wid = tid >> 5, lane = tid & 31;
    const int wm = wid >> 2, wn = wid & 3;
    const uint32_t a_off = (uint32_t)((wm * 32 + (lane & 15)) * LDKB + ((lane >> 4) << 4));
    const uint32_t b_off = (uint32_t)((wn * 32 + (lane & 15)) * F_LDNB + ((lane >> 4) << 4));

    float c[2][4][4];
#pragma unroll
    for (int mi = 0; mi < 2; mi++)
#pragma unroll
        for (int nt = 0; nt < 4; nt++)
#pragma unroll
            for (int q = 0; q < 4; q++) c[mi][nt][q] = 0.f;

    for (int ch = 0; ch < 8; ch++) {
        const int st = ch & 1;
        const uint32_t aH = sbase + F_OFF_A0 + st * F_A_STAGE + a_off;
        const uint32_t bH = sbase + F_OFF_B + b_off + (uint32_t)(ch * 128);
#pragma unroll
        for (int ks = 0; ks < 4; ks++) {
            const uint32_t koff = (uint32_t)(ks * 32);
            uint32_t ah[2][4], bh[2][4];
#pragma unroll
            for (int mi = 0; mi < 2; mi++) {
                uint32_t adr = aH + (uint32_t)(mi * 16 * LDKB) + koff;
                LDSM_X4(ah[mi][0], ah[mi][1], ah[mi][2], ah[mi][3], adr);
            }
#pragma unroll
            for (int np = 0; np < 2; np++) {
                uint32_t adr = bH + (uint32_t)(np * 16 * F_LDNB) + koff;
                LDSM_X4(bh[np][0], bh[np][1], bh[np][2], bh[np][3], adr);
            }
#pragma unroll
            for (int mi = 0; mi < 2; mi++)
#pragma unroll
                for (int np = 0; np < 2; np++)
#pragma unroll
                    for (int t = 0; t < 2; t++) {
                        float* cc = c[mi][np * 2 + t];
                        MMA16816(cc[0], cc[1], cc[2], cc[3],
                                 ah[mi][0], ah[mi][1], ah[mi][2], ah[mi][3],
                                 bh[np][t], bh[np][t + 2]);
                    }
        }
        __syncthreads();

        if (ch + 2 < 8) {
            const uint32_t adst = sbase + F_OFF_A0 + st * F_A_STAGE + crow * LDKB;
            const size_t asrc = asrc_row + (ch + 2) * 128;
            if (avalid) {
#pragma unroll
                for (int j = 0; j < 2; j++) {
                    int s = cseg + 4 * j;
                    CP16(adst + s * 16, cat + asrc + s * 16);
                }
            }
            CP_COMMIT();
            CP_WAIT(1);
            __syncthreads();
        } else if (ch + 1 < 8) {
            CP_WAIT(0);
            __syncthreads();
        }
    }

    // epilogue: bias + lrelu + residual, direct global write
#pragma unroll
    for (int mi = 0; mi < 2; mi++) {
        const int r0 = wm * 32 + mi * 16 + (lane >> 2);
        const int r1 = r0 + 8;
#pragma unroll
        for (int nt = 0; nt < 4; nt++) {
            const int col = wn * 32 + nt * 8 + (lane & 3) * 2;
            const float b0 = sBias[col], b1 = sBias[col + 1];
            int g0 = m0 + r0, g1 = m0 + r1;
            if (g0 < bsz) {
                float2 res = *(const float2*)(xg_old + (size_t)g0 * D + n0 + col);
                float v0 = c[mi][nt][0] + b0, v1 = c[mi][nt][1] + b1;
                v0 = (v0 >= 0.f) ? v0 : 0.01f * v0;
                v1 = (v1 >= 0.f) ? v1 : 0.01f * v1;
                *(float2*)(out + (size_t)g0 * D + n0 + col) =
                    make_float2(v0 + res.x, v1 + res.y);
            }
            if (g1 < bsz) {
                float2 res = *(const float2*)(xg_old + (size_t)g1 * D + n0 + col);
                float v2 = c[mi][nt][2] + b0, v3 = c[mi][nt][3] + b1;
                v2 = (v2 >= 0.f) ? v2 : 0.01f * v2;
                v3 = (v3 >= 0.f) ? v3 : 0.01f * v3;
                *(float2*)(out + (size_t)g1 * D + n0 + col) =
                    make_float2(v2 + res.x, v3 + res.y);
            }
        }
    }
}

// ---------------- launcher ---------------------------------------------------
extern "C" void kernel_launch(void* const* d_in, const int* in_sizes, int n_in,
                              void* d_out, int out_size) {
    const float* xg_old = (const float*)d_in[0];
    const float* x      = (const float*)d_in[1];
    const void*  batch  = d_in[2];
    const float* W_gate = (const float*)d_in[3];
    const float* b_gate = (const float*)d_in[4];
    const float* W_feat = (const float*)d_in[5];
    const float* b_feat = (const float*)d_in[6];
    const float* W_t    = (const float*)d_in[7];
    const float* b_t    = (const float*)d_in[8];
    float*       out    = (float*)d_out;

    int n = in_sizes[2];
    int b = in_sizes[0] / D;
    if (n > N_MAX) n = N_MAX;
    if (b > B_MAX) b = B_MAX;

    cudaFuncSetAttribute(k_main_mma, cudaFuncAttributeMaxDynamicSharedMemorySize,
                         SMEM_MAIN);
    cudaFuncSetAttribute(k_final_mma, cudaFuncAttributeMaxDynamicSharedMemorySize,
                         SMEM_FIN);

    k_detect<<<1, 1>>>(batch, n);
    k_seg<<<(n + 255) / 256, 256>>>(batch, n, b);
    k_convW<<<(D * D + 255) / 256, 256>>>(W_feat);
    k_convWt<<<(2 * D * D + 255) / 256, 256>>>(W_t);
    k_gate<<<(n + 7) / 8, 256>>>(x, W_gate, b_gate, n);
    k_alpha<<<(b + 7) / 8, 256>>>(b);
    k_zero<<<(b * (D / 4) + 255) / 256, 256>>>(b * (D / 4));

    dim3 gm(D / 128, (n + 127) / 128);
    k_main_mma<<<gm, 512, SMEM_MAIN>>>(b_feat, n);

    k_convA<<<(b * D + 255) / 256, 256>>>(xg_old, b);

    dim3 gf(D / 128, (b + 127) / 128);
    k_final_mma<<<gf, 512, SMEM_FIN>>>(xg_old, b_t, out, b);
}